// round 14
// baseline (speedup 1.0000x reference)
#include <cuda_runtime.h>
#include <cuda_bf16.h>
#include <math.h>
#include <cstdint>

#define BB 4
#define NH 8
#define BHD 32
#define HH 96
#define WW 96
#define CC 512
#define DD 64
#define HW 9216
#define MTOT (BB * HW)      // 36864
#define SCALING 0.125f

typedef __nv_bfloat16 bf16;
typedef __nv_bfloat162 bf162;

// ---------------------------------------------------------------------------
// Device-global scratch
// ---------------------------------------------------------------------------
__device__ float d_Er[(size_t)BHD * HW * 96];   // row logits (fp32)
__device__ bf16  d_Ar[(size_t)BHD * HW * 96];   // row probs (bf16)
__device__ float d_O [(size_t)BHD * HW * DD];   // column partial (fp32)
// conv outputs (attention operands, bf16, [bh][px][d])
__device__ bf16 d_tb[(size_t)BHD * HW * DD];
__device__ bf16 d_fb[(size_t)BHD * HW * DD];
__device__ bf16 d_gb[(size_t)BHD * HW * DD];
// bf16 GEMM inputs, K-major [m][c]
__device__ bf16 d_Aq[(size_t)MTOT * CC];
__device__ bf16 d_Av[(size_t)MTOT * CC];
__device__ bf16 d_W [3 * CC * CC];

// ---------------------------------------------------------------------------
// Helpers (generic PTX: sm_80+ features only)
// ---------------------------------------------------------------------------
__device__ __forceinline__ uint32_t smem_u32(const void* p) {
    uint32_t a;
    asm("{ .reg .u64 t; cvta.to.shared.u64 t, %1; cvt.u32.u64 %0, t; }" : "=r"(a) : "l"(p));
    return a;
}
__device__ __forceinline__ void cpa16(uint32_t d, const void* s) {
    asm volatile("cp.async.ca.shared.global [%0], [%1], 16;" :: "r"(d), "l"(s));
}
__device__ __forceinline__ void ldmx4(uint32_t* r, uint32_t addr) {
    asm volatile("ldmatrix.sync.aligned.m8n8.x4.shared.b16 {%0,%1,%2,%3}, [%4];"
        : "=r"(r[0]), "=r"(r[1]), "=r"(r[2]), "=r"(r[3]) : "r"(addr));
}
__device__ __forceinline__ void ldmxt4(uint32_t* r, uint32_t addr) {
    asm volatile("ldmatrix.sync.aligned.m8n8.x4.trans.shared.b16 {%0,%1,%2,%3}, [%4];"
        : "=r"(r[0]), "=r"(r[1]), "=r"(r[2]), "=r"(r[3]) : "r"(addr));
}
__device__ __forceinline__ void ldmx2(uint32_t* r, uint32_t addr) {
    asm volatile("ldmatrix.sync.aligned.m8n8.x2.shared.b16 {%0,%1}, [%2];"
        : "=r"(r[0]), "=r"(r[1]) : "r"(addr));
}
__device__ __forceinline__ void mma16816(float* c, const uint32_t* a,
                                         uint32_t b0, uint32_t b1) {
    asm volatile(
        "mma.sync.aligned.m16n8k16.row.col.f32.bf16.bf16.f32 "
        "{%0,%1,%2,%3}, {%4,%5,%6,%7}, {%8,%9}, {%0,%1,%2,%3};"
        : "+f"(c[0]), "+f"(c[1]), "+f"(c[2]), "+f"(c[3])
        : "r"(a[0]), "r"(a[1]), "r"(a[2]), "r"(a[3]), "r"(b0), "r"(b1));
}

// ---------------------------------------------------------------------------
// Prepass A: transpose + bf16 convert  X[b][c][px] -> A [m][c]  (q and v)
// ---------------------------------------------------------------------------
__global__ void __launch_bounds__(256) toA_kernel(
    const float* __restrict__ Xq, const float* __restrict__ Xv,
    bf16* __restrict__ dq, bf16* __restrict__ dv)
{
    __shared__ float tile[32][33];
    const int t   = threadIdx.x;
    const int px0 = blockIdx.x * 32;
    const int c0  = blockIdx.y * 32;
    const int bz  = blockIdx.z;          // 0..7
    const float* X = (bz < 4) ? Xq : Xv;
    bf16* dst      = (bz < 4) ? dq : dv;
    const int b    = bz & 3;

#pragma unroll
    for (int r = 0; r < 4; r++) {
        int ci = (t >> 5) + r * 8, pj = t & 31;
        tile[ci][pj] = X[((size_t)b * CC + c0 + ci) * HW + px0 + pj];
    }
    __syncthreads();
#pragma unroll
    for (int r = 0; r < 4; r++) {
        int pj = (t >> 5) + r * 8, ci = t & 31;
        dst[((size_t)b * HW + px0 + pj) * CC + c0 + ci] = __float2bfloat16(tile[ci][pj]);
    }
}

__global__ void __launch_bounds__(256) toW_kernel(
    const float* __restrict__ W0, const float* __restrict__ W1,
    const float* __restrict__ W2, bf16* __restrict__ dst)
{
    const int w = blockIdx.y;
    const float* W = (w == 0) ? W0 : (w == 1) ? W1 : W2;
    int i = blockIdx.x * 256 + threadIdx.x;
    if (i < CC * CC) dst[(size_t)w * CC * CC + i] = __float2bfloat16(W[i]);
}

// ---------------------------------------------------------------------------
// Conv GEMM on mma.sync, cp.async 4-stage pipeline. 128x128 tile, K chunk 32.
// (8 warps, warp tile 32x64, 2 CTAs/SM.)
// Fused double-output: gridDim.y may span two weight matrices contiguous in B;
// outputs o>=CC route to dst2/bias2/scale2.
// ---------------------------------------------------------------------------
#define KPAD 40
#define AOFF 0
#define BOFF (128 * KPAD * 2)       // 10240
#define STGB (2 * 128 * KPAD * 2)   // 20480
#define NSTG 4

__global__ void __launch_bounds__(256) conv_wmma_kernel(
    const bf16* __restrict__ A, const bf16* __restrict__ B,
    const float* __restrict__ bias, float scale, bf16* __restrict__ dst,
    const float* __restrict__ bias2, float scale2, bf16* __restrict__ dst2)
{
    extern __shared__ __align__(16) bf16 cs[];
    const uint32_t sb = smem_u32(cs);

    const int tid  = threadIdx.x;
    const int lane = tid & 31;
    const int warp = tid >> 5;
    const int wm   = warp & 3;
    const int wn   = warp >> 2;

    const int M0 = blockIdx.x * 128;
    const int o0 = blockIdx.y * 128;         // global output offset into B

    const int side = (o0 >= CC);
    const float* bb = side ? bias2 : bias;
    bf16* dd        = side ? dst2  : dst;
    const float sc  = side ? scale2 : scale;
    const int oo0   = o0 - side * CC;        // local output offset

    const int crow = tid >> 2, cseg = tid & 3;
    const bf16* pA = A + (size_t)(M0 + crow) * CC + cseg * 8;
    const bf16* pB = B + (size_t)(o0 + crow) * CC + cseg * 8;
    const uint32_t sdst = (crow * KPAD + cseg * 8) * 2;
    const uint32_t rstep = 64 * KPAD * 2;

    float acc[2][8][4];
#pragma unroll
    for (int mi = 0; mi < 2; mi++)
#pragma unroll
        for (int nf = 0; nf < 8; nf++)
#pragma unroll
            for (int k = 0; k < 4; k++) acc[mi][nf][k] = 0.f;

    const int lrow = lane & 15;
    const int lsel = (lane >> 4) * 8;

    // prologue: stage chunks 0..2
#pragma unroll
    for (int p = 0; p < 3; p++) {
        uint32_t so = sb + p * STGB + sdst;
#pragma unroll
        for (int r = 0; r < 2; r++) {
            const size_t go = (size_t)r * 64 * CC + p * 32;
            cpa16(so + AOFF + r * rstep, pA + go);
            cpa16(so + BOFF + r * rstep, pB + go);
        }
        asm volatile("cp.async.commit_group;");
    }

    for (int ch = 0; ch < 16; ch++) {
        if (ch + 3 < 16) {
            uint32_t so = sb + ((ch + 3) % NSTG) * STGB + sdst;
#pragma unroll
            for (int r = 0; r < 2; r++) {
                const size_t go = (size_t)r * 64 * CC + (ch + 3) * 32;
                cpa16(so + AOFF + r * rstep, pA + go);
                cpa16(so + BOFF + r * rstep, pB + go);
            }
            asm volatile("cp.async.commit_group;");
            asm volatile("cp.async.wait_group 3;");
        } else if (ch + 2 < 16) {
            asm volatile("cp.async.wait_group 2;");
        } else if (ch + 1 < 16) {
            asm volatile("cp.async.wait_group 1;");
        } else {
            asm volatile("cp.async.wait_group 0;");
        }
        __syncthreads();

        const uint32_t stb = sb + (ch % NSTG) * STGB;
#pragma unroll
        for (int ks = 0; ks < 2; ks++) {
            const int kc = ks * 16 + lsel;
            uint32_t a[2][4];
#pragma unroll
            for (int mi = 0; mi < 2; mi++)
                ldmx4(a[mi], stb + AOFF + ((wm * 32 + mi * 16 + lrow) * KPAD + kc) * 2);
#pragma unroll
            for (int np = 0; np < 4; np++) {
                uint32_t b[4];
                ldmx4(b, stb + BOFF + ((wn * 64 + np * 16 + lrow) * KPAD + kc) * 2);
#pragma unroll
                for (int mi = 0; mi < 2; mi++)
#pragma unroll
                    for (int hf = 0; hf < 2; hf++)
                        mma16816(acc[mi][np * 2 + hf], a[mi], b[hf], b[2 + hf]);
            }
        }
        __syncthreads();
    }

#pragma unroll
    for (int mi = 0; mi < 2; mi++) {
        const int m  = M0 + wm * 32 + mi * 16 + (lane >> 2);
        const int b  = m / HW;
        const int pp = m % HW;
#pragma unroll
        for (int nf = 0; nf < 8; nf++) {
            const int o = oo0 + wn * 64 + nf * 8 + (lane & 3) * 2;
            const int h = o >> 6, d = o & 63;
            const float b0 = bb[o], b1 = bb[o + 1];
            size_t i0 = ((size_t)(b * NH + h) * HW + pp) * DD + d;
            size_t i1 = i0 + (size_t)8 * DD;
            *(bf162*)(dd + i0) = bf162{
                __float2bfloat16((acc[mi][nf][0] + b0) * sc),
                __float2bfloat16((acc[mi][nf][1] + b1) * sc)};
            *(bf162*)(dd + i1) = bf162{
                __float2bfloat16((acc[mi][nf][2] + b0) * sc),
                __float2bfloat16((acc[mi][nf][3] + b1) * sc)};
        }
    }
}

// ---------------------------------------------------------------------------
// Logits mma: C[96][96] = A[96][64] * B[96][64]^T, bf16, pitch 72.
// ---------------------------------------------------------------------------
#define PBF 72
#define ABUF 13824   // 96*72*2

__device__ __forceinline__ void logits_mma(
    uint32_t sb, uint32_t aOff, uint32_t bOff, int lane, int wm, int wn,
    float acc[3][3][4])
{
    const int l15 = lane & 15;
#pragma unroll
    for (int ks = 0; ks < 4; ks++) {
        const int kc = ks * 16;
        uint32_t a[3][4];
#pragma unroll
        for (int mt = 0; mt < 3; mt++)
            ldmx4(a[mt], sb + aOff +
                ((wm * 48 + mt * 16 + l15) * PBF + kc + (lane >> 4) * 8) * 2);
#pragma unroll
        for (int nt = 0; nt < 3; nt++) {
            uint32_t b[2];
            ldmx2(b, sb + bOff +
                ((wn * 24 + nt * 8 + (l15 & 7)) * PBF + kc + ((l15 >> 3) & 1) * 8) * 2);
#pragma unroll
            for (int mt = 0; mt < 3; mt++)
                mma16816(acc[mt][nt], a[mt], b[0], b[1]);
        }
    }
}

// Output mma: C[96][64] = A[96][96](pitch APITCH bf16) * B[96][64](pitch 72, trans)
#define PA 104

template <int APITCH>
__device__ __forceinline__ void probs_mma(
    uint32_t sb, uint32_t aOff, uint32_t gOff, int lane, int wm, int wn,
    float acc[3][2][4])
{
    const int l15 = lane & 15;
#pragma unroll
    for (int ks = 0; ks < 6; ks++) {
        const int kc = ks * 16;
        uint32_t a[3][4];
#pragma unroll
        for (int mt = 0; mt < 3; mt++)
            ldmx4(a[mt], sb + aOff +
                ((wm * 48 + mt * 16 + l15) * APITCH + kc + (lane >> 4) * 8) * 2);
        uint32_t bt[4];
        ldmxt4(bt, sb + gOff + ((kc + l15) * PBF + wn * 16 + (lane >> 4) * 8) * 2);
#pragma unroll
        for (int mt = 0; mt < 3; mt++) {
            mma16816(acc[mt][0], a[mt], bt[0], bt[1]);
            mma16816(acc[mt][1], a[mt], bt[2], bt[3]);
        }
    }
}

// ---------------------------------------------------------------------------
// Kernel 2: row logits -> d_Er. Block (y, bh).
// ---------------------------------------------------------------------------
__global__ void __launch_bounds__(256) erow_kernel()
{
    extern __shared__ __align__(16) char smem[];
    const uint32_t sb = smem_u32(smem);

    const int y = blockIdx.x, bh = blockIdx.y, tid = threadIdx.x;
    const int lane = tid & 31, warp = tid >> 5;

    const size_t off = ((size_t)bh * HW + y * 96) * DD;
    const bf16* srcs[2] = {d_tb + off, d_fb + off};
#pragma unroll
    for (int a = 0; a < 2; a++)
#pragma unroll
        for (int k = 0; k < 3; k++) {
            int idx = tid + k * 256;
            int row = idx >> 3, c = (idx & 7) * 8;
            *(uint4*)(smem + a * ABUF + (row * PBF + c) * 2) =
                *(const uint4*)(srcs[a] + (size_t)idx * 8);
        }
    __syncthreads();

    float acc[3][3][4];
#pragma unroll
    for (int mt = 0; mt < 3; mt++)
#pragma unroll
        for (int nt = 0; nt < 3; nt++)
#pragma unroll
            for (int k = 0; k < 4; k++) acc[mt][nt][k] = 0.f;

    const int wm = warp >> 2, wn = warp & 3;
    logits_mma(sb, 0, ABUF, lane, wm, wn, acc);

    float* Eb = d_Er + ((size_t)bh * HH + y) * WW * 96;
#pragma unroll
    for (int mt = 0; mt < 3; mt++)
#pragma unroll
        for (int nt = 0; nt < 3; nt++) {
            const int x0 = wm * 48 + mt * 16 + (lane >> 2);
            const int i0 = wn * 24 + nt * 8 + (lane & 3) * 2;
            *(float2*)&Eb[(size_t)x0 * 96 + i0]       = float2{acc[mt][nt][0], acc[mt][nt][1]};
            *(float2*)&Eb[(size_t)(x0 + 8) * 96 + i0] = float2{acc[mt][nt][2], acc[mt][nt][3]};
        }
}

// ---------------------------------------------------------------------------
// Kernel 3 (fused): per (x, bh): col logits (mma, SMEM) + softmax(192)
//   with direct prob emission + column output (mma) -> d_O.
// SMEM phases:
//   P1: t@0, f@13824 (27648) | Ec f32 [96][100] @38400 (38400)
//   P2: Er f32 [96][100] @0 | g bf16 [96][72] @76800 (13824)
//   P3: Acol bf16 [96] pitch 200 bf16 (400 B) @0 — in-place over Er rows.
// total 90624 B
// ---------------------------------------------------------------------------
#define EC_OFF 38400
#define G_OFF  76800
#define PAC 200   // Ac pitch in bf16 (= Er row pitch of 400 B)

__global__ void __launch_bounds__(256) fusedcol_kernel()
{
    extern __shared__ __align__(16) char smem[];
    const uint32_t sb = smem_u32(smem);

    const int x = blockIdx.x, bh = blockIdx.y, tid = threadIdx.x;
    const int lane = tid & 31, warp = tid >> 5;
    const int wm = warp >> 2, wn = warp & 3;

    // P1 load: t/f columns (row stride WW*DD)
    {
        const size_t off = ((size_t)bh * HW + x) * DD;
        const bf16* srcs[2] = {d_tb + off, d_fb + off};
#pragma unroll
        for (int a = 0; a < 2; a++)
#pragma unroll
            for (int k = 0; k < 3; k++) {
                int idx = tid + k * 256;
                int row = idx >> 3, c = (idx & 7) * 8;
                *(uint4*)(smem + a * ABUF + (row * PBF + c) * 2) =
                    *(const uint4*)(srcs[a] + (size_t)row * (WW * DD) + c);
            }
    }
    __syncthreads();

    // column logits -> Ec with diagonal mask
    {
        float acc[3][3][4];
#pragma unroll
        for (int mt = 0; mt < 3; mt++)
#pragma unroll
            for (int nt = 0; nt < 3; nt++)
#pragma unroll
                for (int k = 0; k < 4; k++) acc[mt][nt][k] = 0.f;

        logits_mma(sb, 0, ABUF, lane, wm, wn, acc);

        float (*Ec)[100] = (float(*)[100])(smem + EC_OFF);
#pragma unroll
        for (int mt = 0; mt < 3; mt++)
#pragma unroll
            for (int nt = 0; nt < 3; nt++) {
                const int y0 = wm * 48 + mt * 16 + (lane >> 2);
                const int i0 = wn * 24 + nt * 8 + (lane & 3) * 2;
                Ec[y0][i0]     = (i0     == y0)     ? -INFINITY : acc[mt][nt][0];
                Ec[y0][i0 + 1] = (i0 + 1 == y0)     ? -INFINITY : acc[mt][nt][1];
                Ec[y0 + 8][i0]     = (i0     == y0 + 8) ? -INFINITY : acc[mt][nt][2];
                Ec[y0 + 8][i0 + 1] = (i0 + 1 == y0 + 8) ? -INFINITY : acc[mt][nt][3];
            }
    }
    __syncthreads();   // t/f reads done, Ec complete

    // P2 loads: Er slice + g column
    {
        float (*Er)[100] = (float(*)[100])smem;
        const float* eb = d_Er + (size_t)bh * HH * WW * 96 + (size_t)x * 96;
        for (int idx = tid; idx < 96 * 24; idx += 256) {
            int r = idx / 24, c4 = idx % 24;
            *(float4*)&Er[r][c4 * 4] =
                *(const float4*)(eb + (size_t)r * (WW * 96) + c4 * 4);
        }
        const bf16* gsrc = d_gb + ((size_t)bh * HW + x) * DD;
#pragma unroll
        for (int k = 0; k < 3; k++) {
            int idx = tid + k * 256;
            int row = idx >> 3, c = (idx & 7) * 8;
            *(uint4*)(smem + G_OFF + (row * PBF + c) * 2) =
                *(const uint4*)(gsrc + (size_t)row * (WW * DD) + c);
        }
    }
    __syncthreads();

    // softmax over concat(Er, Ec) — warp per row; emits probs directly
    {
        float (*Er)[100] = (float(*)[100])smem;
        float (*Ec)[100] = (float(*)[100])(smem + EC_OFF);
        bf16* Ac = (bf16*)smem;
#pragma unroll 1
        for (int rr = 0; rr < 12; rr++) {
            const int r = warp * 12 + rr;
            float vr[3], vc[3];
#pragma unroll
            for (int k = 0; k < 3; k++) { vr[k] = Er[r][lane + k * 32]; vc[k] = Ec[r][lane + k * 32]; }
            float m = -INFINITY;
#pragma unroll
            for (int k = 0; k < 3; k++) m = fmaxf(m, fmaxf(vr[k], vc[k]));
#pragma unroll
            for (int off = 16; off; off >>= 1) m = fmaxf(m, __shfl_xor_sync(0xffffffffu, m, off));
            float s = 0.f;
#pragma unroll
            for (int k = 0; k < 3; k++) {
                vr[k] = __expf(vr[k] - m); vc[k] = __expf(vc[k] - m);
                s += vr[k] + vc[k];
            }
#pragma unroll
            for (int off = 16; off; off >>= 1) s += __shfl_xor_sync(0xffffffffu, s, off);
            const float inv = 1.f / s;
            bf16* arow = d_Ar + ((size_t)(bh * HH + r) * WW + x) * 96;
            bf16* acrow = Ac + r * PAC;
#pragma unroll
            for (int k = 0; k < 3; k++) {
                arow[lane + k * 32]  = __float2bfloat16(vr[k] * inv);
                acrow[lane + k * 32] = __float2bfloat16(vc[k] * inv);
            }
        }
    }
    __syncthreads();

    // column output mma -> d_O
    {
        float acc[3][2][4];
#pragma unroll
        for (int mt = 0; mt < 3; mt++)
#pragma unroll
            for (int nt = 0; nt < 2; nt++)
#pragma unroll
                for (int k = 0; k < 4; k++) acc[mt][nt][k] = 0.f;

        probs_mma<PAC>(sb, 0, G_OFF, lane, wm, wn, acc);

#pragma unroll
        for (int mt = 0; mt < 3; mt++)
#pragma unroll
            for (int nt = 0; nt < 2; nt++) {
                const int yv = wm * 48 + mt * 16 + (lane >> 2);
                const int d0 = wn * 16 + nt * 8 + (lane & 3) * 2;
                float* ob = d_O + ((size_t)(bh * HH + yv) * WW + x) * DD + d0;
                *(float2*)ob = float2{acc[mt][nt][0], acc[mt][nt][1]};
                *(float2*)(ob + (size_t)8 * WW * DD) = float2{acc[mt][nt][2], acc[mt][nt][3]};
            }
    }
}

// ---------------------------------------------------------------------------
// Kernel 4: row output (mma) + combine + residual. Block (y, bh).
// ---------------------------------------------------------------------------
__global__ void __launch_bounds__(256) rowout_kernel(
    const float* __restrict__ v, const float* __restrict__ gamma,
    float* __restrict__ out)
{
    __shared__ __align__(16) bf16 Asm[96][PA];
    __shared__ __align__(16) bf16 gsm[96][PBF];

    const int y = blockIdx.x, bh = blockIdx.y, tid = threadIdx.x;
    const int lane = tid & 31, warp = tid >> 5;
    const int wm = warp >> 2, wn = warp & 3;

    const bf16* ab = d_Ar + ((size_t)bh * HH + y) * WW * 96;
    for (int idx = tid; idx < 96 * 12; idx += 256) {
        int row = idx / 12, c8 = idx % 12;
        *(uint4*)&Asm[row][c8 * 8] = *(const uint4*)(ab + (size_t)row * 96 + c8 * 8);
    }
    const bf16* gb = d_gb + ((size_t)bh * HH + y) * WW * DD;
#pragma unroll
    for (int k = 0; k < 3; k++) {
        int idx = tid + k * 256;
        int row = idx >> 3, c = (idx & 7) * 8;
        *(uint4*)&gsm[row][c] = *(const uint4*)(gb + (size_t)idx * 8);
    }
    __syncthreads();

    float acc[3][2][4];
#pragma unroll
    for (int mt = 0; mt < 3; mt++)
#pragma unroll
        for (int nt = 0; nt < 2; nt++)
#pragma unroll
            for (int k = 0; k < 4; k++) acc[mt][nt][k] = 0.f;

    const uint32_t sbA = smem_u32(Asm);
    const uint32_t sbG = smem_u32(gsm);
    probs_mma<PA>(sbA, 0, sbG - sbA, lane, wm, wn, acc);

    const float gam = gamma[0];
    const int b = bh >> 3, h = bh & 7;
    const float* colp = d_O + ((size_t)bh * HH + y) * WW * DD;

#pragma unroll
    for (int mt = 0; mt < 3; mt++)
#pragma unroll
        for (int nt = 0; nt < 2; nt++) {
            const int x0 = wm * 48 + mt * 16 + (lane >> 2);
            const int d0 = wn * 16 + nt * 8 + (lane & 3) * 2;
#pragma unroll
            for (int rh = 0; rh < 2; rh++) {
                const int xx = x0 + rh * 8;
                float2 cp = *(const float2*)(colp + (size_t)xx * DD + d0);
                float s0 = acc[mt][nt][rh * 2]     + cp.x;
                float s1 = acc[mt][nt][rh * 2 + 1] + cp.y;
                size_t oa0 = (((size_t)(b * CC + h * 64 + d0)) * HH + y) * WW + xx;
                size_t oa1 = oa0 + (size_t)HW;
                out[oa0] = gam * s0 + v[oa0];
                out[oa1] = gam * s1 + v[oa1];
            }
        }
}

// ---------------------------------------------------------------------------
extern "C" void kernel_launch(void* const* d_in, const int* in_sizes, int n_in,
                              void* d_out, int out_size)
{
    const float* q     = (const float*)d_in[0];
    const float* v     = (const float*)d_in[1];
    const float* Wq    = (const float*)d_in[2];
    const float* bq    = (const float*)d_in[3];
    const float* Wk    = (const float*)d_in[4];
    const float* bk    = (const float*)d_in[5];
    const float* Wv    = (const float*)d_in[6];
    const float* bv    = (const float*)d_in[7];
    const float* gamma = (const float*)d_in[8];
    float* out = (float*)d_out;

    static bf16 *pAq = nullptr, *pAv, *pW, *pT, *pF, *pG;
    static cudaStream_t s2;
    static cudaEvent_t evFork, evA, evW, evJoin;
    if (!pAq) {
        cudaGetSymbolAddress((void**)&pAq, d_Aq);
        cudaGetSymbolAddress((void**)&pAv, d_Av);
        cudaGetSymbolAddress((void**)&pW,  d_W);
        cudaGetSymbolAddress((void**)&pT,  d_tb);
        cudaGetSymbolAddress((void**)&pF,  d_fb);
        cudaGetSymbolAddress((void**)&pG,  d_gb);
        cudaStreamCreateWithFlags(&s2, cudaStreamNonBlocking);
        cudaEventCreateWithFlags(&evFork, cudaEventDisableTiming);
        cudaEventCreateWithFlags(&evA,    cudaEventDisableTiming);
        cudaEventCreateWithFlags(&evW,    cudaEventDisableTiming);
        cudaEventCreateWithFlags(&evJoin, cudaEventDisableTiming);
    }

    const int smConv = NSTG * STGB;  // 81920
    const int smE    = 2 * ABUF;     // 27648
    const int smF    = G_OFF + ABUF; // 90624
    static bool attrs_set = false;
    if (!attrs_set) {
        cudaFuncSetAttribute(conv_wmma_kernel, cudaFuncAttributeMaxDynamicSharedMemorySize, smConv);
        cudaFuncSetAttribute(erow_kernel,      cudaFuncAttributeMaxDynamicSharedMemorySize, smE);
        cudaFuncSetAttribute(fusedcol_kernel,  cudaFuncAttributeMaxDynamicSharedMemorySize, smF);
        attrs_set = true;
    }

    // Fork s2 from the capture stream FIRST (capture-legality requirement)
    cudaEventRecord(evFork, 0);
    cudaStreamWaitEvent(s2, evFork, 0);

    // Prepasses: toW on s2 concurrent with toA on main stream
    dim3 wGrid((CC * CC + 255) / 256, 3);
    toW_kernel<<<wGrid, 256, 0, s2>>>(Wq, Wk, Wv, pW);
    cudaEventRecord(evW, s2);

    dim3 spGrid(HW / 32, CC / 32, 2 * BB);
    toA_kernel<<<spGrid, 256>>>(q, v, pAq, pAv);
    cudaEventRecord(evA, 0);

    // conv-g on s2 (needs toW [same stream] + toA)
    cudaStreamWaitEvent(s2, evA, 0);
    dim3 cg(MTOT / 128, CC / 128);   // 288 x 4
    conv_wmma_kernel<<<cg, 256, smConv, s2>>>(pAv, pW + 2 * CC * CC, bv, 1.0f, pG,
                                              bv, 1.0f, pG);

    // fused t+f conv on main stream (needs toA [same stream] + toW)
    cudaStreamWaitEvent(0, evW, 0);
    dim3 ctf(MTOT / 128, 2 * CC / 128);  // 288 x 8 over [Wq;Wk]
    conv_wmma_kernel<<<ctf, 256, smConv>>>(pAq, pW, bq, SCALING, pT,
                                           bk, 1.0f, pF);

    // erow (needs t, f) overlaps tail of conv-g
    dim3 attnGrid(96, BHD);
    erow_kernel<<<attnGrid, 256, smE>>>();

    cudaEventRecord(evJoin, s2);
    cudaStreamWaitEvent(0, evJoin, 0);

    // Remaining attention
    fusedcol_kernel<<<attnGrid, 256, smF>>>();
    rowout_kernel<<<attnGrid, 256>>>(v, gamma, out);
}

// round 15
// speedup vs baseline: 1.0478x; 1.0478x over previous
#include <cuda_runtime.h>
#include <cuda_bf16.h>
#include <math.h>
#include <cstdint>

#define BB 4
#define NH 8
#define BHD 32
#define HH 96
#define WW 96
#define CC 512
#define DD 64
#define HW 9216
#define MTOT (BB * HW)      // 36864
#define SCALING 0.125f

typedef __nv_bfloat16 bf16;
typedef __nv_bfloat162 bf162;

// ---------------------------------------------------------------------------
// Device-global scratch
// ---------------------------------------------------------------------------
__device__ bf16 d_Er[(size_t)BHD * HW * 96];   // row logits (bf16)
__device__ bf16 d_Ar[(size_t)BHD * HW * 96];   // row probs (bf16)
__device__ bf16 d_O [(size_t)BHD * HW * DD];   // column partial (bf16)
// conv outputs (attention operands, bf16, [bh][px][d])
__device__ bf16 d_tb[(size_t)BHD * HW * DD];
__device__ bf16 d_fb[(size_t)BHD * HW * DD];
__device__ bf16 d_gb[(size_t)BHD * HW * DD];
// bf16 GEMM inputs, K-major [m][c]
__device__ bf16 d_Aq[(size_t)MTOT * CC];
__device__ bf16 d_Av[(size_t)MTOT * CC];
__device__ bf16 d_W [3 * CC * CC];

// ---------------------------------------------------------------------------
// Helpers (generic PTX: sm_80+ features only)
// ---------------------------------------------------------------------------
__device__ __forceinline__ uint32_t smem_u32(const void* p) {
    uint32_t a;
    asm("{ .reg .u64 t; cvta.to.shared.u64 t, %1; cvt.u32.u64 %0, t; }" : "=r"(a) : "l"(p));
    return a;
}
__device__ __forceinline__ void cpa16(uint32_t d, const void* s) {
    asm volatile("cp.async.ca.shared.global [%0], [%1], 16;" :: "r"(d), "l"(s));
}
__device__ __forceinline__ void ldmx4(uint32_t* r, uint32_t addr) {
    asm volatile("ldmatrix.sync.aligned.m8n8.x4.shared.b16 {%0,%1,%2,%3}, [%4];"
        : "=r"(r[0]), "=r"(r[1]), "=r"(r[2]), "=r"(r[3]) : "r"(addr));
}
__device__ __forceinline__ void ldmxt4(uint32_t* r, uint32_t addr) {
    asm volatile("ldmatrix.sync.aligned.m8n8.x4.trans.shared.b16 {%0,%1,%2,%3}, [%4];"
        : "=r"(r[0]), "=r"(r[1]), "=r"(r[2]), "=r"(r[3]) : "r"(addr));
}
__device__ __forceinline__ void ldmx2(uint32_t* r, uint32_t addr) {
    asm volatile("ldmatrix.sync.aligned.m8n8.x2.shared.b16 {%0,%1}, [%2];"
        : "=r"(r[0]), "=r"(r[1]) : "r"(addr));
}
__device__ __forceinline__ void mma16816(float* c, const uint32_t* a,
                                         uint32_t b0, uint32_t b1) {
    asm volatile(
        "mma.sync.aligned.m16n8k16.row.col.f32.bf16.bf16.f32 "
        "{%0,%1,%2,%3}, {%4,%5,%6,%7}, {%8,%9}, {%0,%1,%2,%3};"
        : "+f"(c[0]), "+f"(c[1]), "+f"(c[2]), "+f"(c[3])
        : "r"(a[0]), "r"(a[1]), "r"(a[2]), "r"(a[3]), "r"(b0), "r"(b1));
}

// ---------------------------------------------------------------------------
// Prepass A: transpose + bf16 convert  X[b][c][px] -> A [m][c]  (q and v)
// ---------------------------------------------------------------------------
__global__ void __launch_bounds__(256) toA_kernel(
    const float* __restrict__ Xq, const float* __restrict__ Xv,
    bf16* __restrict__ dq, bf16* __restrict__ dv)
{
    __shared__ float tile[32][33];
    const int t   = threadIdx.x;
    const int px0 = blockIdx.x * 32;
    const int c0  = blockIdx.y * 32;
    const int bz  = blockIdx.z;          // 0..7
    const float* X = (bz < 4) ? Xq : Xv;
    bf16* dst      = (bz < 4) ? dq : dv;
    const int b    = bz & 3;

#pragma unroll
    for (int r = 0; r < 4; r++) {
        int ci = (t >> 5) + r * 8, pj = t & 31;
        tile[ci][pj] = X[((size_t)b * CC + c0 + ci) * HW + px0 + pj];
    }
    __syncthreads();
#pragma unroll
    for (int r = 0; r < 4; r++) {
        int pj = (t >> 5) + r * 8, ci = t & 31;
        dst[((size_t)b * HW + px0 + pj) * CC + c0 + ci] = __float2bfloat16(tile[ci][pj]);
    }
}

__global__ void __launch_bounds__(256) toW_kernel(
    const float* __restrict__ W0, const float* __restrict__ W1,
    const float* __restrict__ W2, bf16* __restrict__ dst)
{
    const int w = blockIdx.y;
    const float* W = (w == 0) ? W0 : (w == 1) ? W1 : W2;
    int i = blockIdx.x * 256 + threadIdx.x;
    if (i < CC * CC) dst[(size_t)w * CC * CC + i] = __float2bfloat16(W[i]);
}

// ---------------------------------------------------------------------------
// Conv GEMM on mma.sync, cp.async 4-stage pipeline. 128x128 tile, K chunk 32.
// (8 warps, warp tile 32x64, 2 CTAs/SM.)  Fused double-output over [W1;W2].
// ---------------------------------------------------------------------------
#define KPAD 40
#define AOFF 0
#define BOFF (128 * KPAD * 2)       // 10240
#define STGB (2 * 128 * KPAD * 2)   // 20480
#define NSTG 4

__global__ void __launch_bounds__(256) conv_wmma_kernel(
    const bf16* __restrict__ A, const bf16* __restrict__ B,
    const float* __restrict__ bias, float scale, bf16* __restrict__ dst,
    const float* __restrict__ bias2, float scale2, bf16* __restrict__ dst2)
{
    extern __shared__ __align__(16) bf16 cs[];
    const uint32_t sb = smem_u32(cs);

    const int tid  = threadIdx.x;
    const int lane = tid & 31;
    const int warp = tid >> 5;
    const int wm   = warp & 3;
    const int wn   = warp >> 2;

    const int M0 = blockIdx.x * 128;
    const int o0 = blockIdx.y * 128;

    const int side = (o0 >= CC);
    const float* bb = side ? bias2 : bias;
    bf16* dd        = side ? dst2  : dst;
    const float sc  = side ? scale2 : scale;
    const int oo0   = o0 - side * CC;

    const int crow = tid >> 2, cseg = tid & 3;
    const bf16* pA = A + (size_t)(M0 + crow) * CC + cseg * 8;
    const bf16* pB = B + (size_t)(o0 + crow) * CC + cseg * 8;
    const uint32_t sdst = (crow * KPAD + cseg * 8) * 2;
    const uint32_t rstep = 64 * KPAD * 2;

    float acc[2][8][4];
#pragma unroll
    for (int mi = 0; mi < 2; mi++)
#pragma unroll
        for (int nf = 0; nf < 8; nf++)
#pragma unroll
            for (int k = 0; k < 4; k++) acc[mi][nf][k] = 0.f;

    const int lrow = lane & 15;
    const int lsel = (lane >> 4) * 8;

#pragma unroll
    for (int p = 0; p < 3; p++) {
        uint32_t so = sb + p * STGB + sdst;
#pragma unroll
        for (int r = 0; r < 2; r++) {
            const size_t go = (size_t)r * 64 * CC + p * 32;
            cpa16(so + AOFF + r * rstep, pA + go);
            cpa16(so + BOFF + r * rstep, pB + go);
        }
        asm volatile("cp.async.commit_group;");
    }

    for (int ch = 0; ch < 16; ch++) {
        if (ch + 3 < 16) {
            uint32_t so = sb + ((ch + 3) % NSTG) * STGB + sdst;
#pragma unroll
            for (int r = 0; r < 2; r++) {
                const size_t go = (size_t)r * 64 * CC + (ch + 3) * 32;
                cpa16(so + AOFF + r * rstep, pA + go);
                cpa16(so + BOFF + r * rstep, pB + go);
            }
            asm volatile("cp.async.commit_group;");
            asm volatile("cp.async.wait_group 3;");
        } else if (ch + 2 < 16) {
            asm volatile("cp.async.wait_group 2;");
        } else if (ch + 1 < 16) {
            asm volatile("cp.async.wait_group 1;");
        } else {
            asm volatile("cp.async.wait_group 0;");
        }
        __syncthreads();

        const uint32_t stb = sb + (ch % NSTG) * STGB;
#pragma unroll
        for (int ks = 0; ks < 2; ks++) {
            const int kc = ks * 16 + lsel;
            uint32_t a[2][4];
#pragma unroll
            for (int mi = 0; mi < 2; mi++)
                ldmx4(a[mi], stb + AOFF + ((wm * 32 + mi * 16 + lrow) * KPAD + kc) * 2);
#pragma unroll
            for (int np = 0; np < 4; np++) {
                uint32_t b[4];
                ldmx4(b, stb + BOFF + ((wn * 64 + np * 16 + lrow) * KPAD + kc) * 2);
#pragma unroll
                for (int mi = 0; mi < 2; mi++)
#pragma unroll
                    for (int hf = 0; hf < 2; hf++)
                        mma16816(acc[mi][np * 2 + hf], a[mi], b[hf], b[2 + hf]);
            }
        }
        __syncthreads();
    }

#pragma unroll
    for (int mi = 0; mi < 2; mi++) {
        const int m  = M0 + wm * 32 + mi * 16 + (lane >> 2);
        const int b  = m / HW;
        const int pp = m % HW;
#pragma unroll
        for (int nf = 0; nf < 8; nf++) {
            const int o = oo0 + wn * 64 + nf * 8 + (lane & 3) * 2;
            const int h = o >> 6, d = o & 63;
            const float b0 = bb[o], b1 = bb[o + 1];
            size_t i0 = ((size_t)(b * NH + h) * HW + pp) * DD + d;
            size_t i1 = i0 + (size_t)8 * DD;
            *(bf162*)(dd + i0) = bf162{
                __float2bfloat16((acc[mi][nf][0] + b0) * sc),
                __float2bfloat16((acc[mi][nf][1] + b1) * sc)};
            *(bf162*)(dd + i1) = bf162{
                __float2bfloat16((acc[mi][nf][2] + b0) * sc),
                __float2bfloat16((acc[mi][nf][3] + b1) * sc)};
        }
    }
}

// ---------------------------------------------------------------------------
// Logits mma: C[96][96] = A[96][64] * B[96][64]^T, bf16, pitch 72.
// ---------------------------------------------------------------------------
#define PBF 72
#define ABUF 13824   // 96*72*2

__device__ __forceinline__ void logits_mma(
    uint32_t sb, uint32_t aOff, uint32_t bOff, int lane, int wm, int wn,
    float acc[3][3][4])
{
    const int l15 = lane & 15;
#pragma unroll
    for (int ks = 0; ks < 4; ks++) {
        const int kc = ks * 16;
        uint32_t a[3][4];
#pragma unroll
        for (int mt = 0; mt < 3; mt++)
            ldmx4(a[mt], sb + aOff +
                ((wm * 48 + mt * 16 + l15) * PBF + kc + (lane >> 4) * 8) * 2);
#pragma unroll
        for (int nt = 0; nt < 3; nt++) {
            uint32_t b[2];
            ldmx2(b, sb + bOff +
                ((wn * 24 + nt * 8 + (l15 & 7)) * PBF + kc + ((l15 >> 3) & 1) * 8) * 2);
#pragma unroll
            for (int mt = 0; mt < 3; mt++)
                mma16816(acc[mt][nt], a[mt], b[0], b[1]);
        }
    }
}

// Output mma: C[96][64] = A[96][96](pitch APITCH bf16) * B[96][64](pitch 72, trans)
#define PA 104

template <int APITCH>
__device__ __forceinline__ void probs_mma(
    uint32_t sb, uint32_t aOff, uint32_t gOff, int lane, int wm, int wn,
    float acc[3][2][4])
{
    const int l15 = lane & 15;
#pragma unroll
    for (int ks = 0; ks < 6; ks++) {
        const int kc = ks * 16;
        uint32_t a[3][4];
#pragma unroll
        for (int mt = 0; mt < 3; mt++)
            ldmx4(a[mt], sb + aOff +
                ((wm * 48 + mt * 16 + l15) * APITCH + kc + (lane >> 4) * 8) * 2);
        uint32_t bt[4];
        ldmxt4(bt, sb + gOff + ((kc + l15) * PBF + wn * 16 + (lane >> 4) * 8) * 2);
#pragma unroll
        for (int mt = 0; mt < 3; mt++) {
            mma16816(acc[mt][0], a[mt], bt[0], bt[1]);
            mma16816(acc[mt][1], a[mt], bt[2], bt[3]);
        }
    }
}

// ---------------------------------------------------------------------------
// Kernel 2: row logits -> d_Er (bf16). Block (y, bh).
// ---------------------------------------------------------------------------
__global__ void __launch_bounds__(256) erow_kernel()
{
    extern __shared__ __align__(16) char smem[];
    const uint32_t sb = smem_u32(smem);

    const int y = blockIdx.x, bh = blockIdx.y, tid = threadIdx.x;
    const int lane = tid & 31, warp = tid >> 5;

    const size_t off = ((size_t)bh * HW + y * 96) * DD;
    const bf16* srcs[2] = {d_tb + off, d_fb + off};
#pragma unroll
    for (int a = 0; a < 2; a++)
#pragma unroll
        for (int k = 0; k < 3; k++) {
            int idx = tid + k * 256;
            int row = idx >> 3, c = (idx & 7) * 8;
            *(uint4*)(smem + a * ABUF + (row * PBF + c) * 2) =
                *(const uint4*)(srcs[a] + (size_t)idx * 8);
        }
    __syncthreads();

    float acc[3][3][4];
#pragma unroll
    for (int mt = 0; mt < 3; mt++)
#pragma unroll
        for (int nt = 0; nt < 3; nt++)
#pragma unroll
            for (int k = 0; k < 4; k++) acc[mt][nt][k] = 0.f;

    const int wm = warp >> 2, wn = warp & 3;
    logits_mma(sb, 0, ABUF, lane, wm, wn, acc);

    bf16* Eb = d_Er + ((size_t)bh * HH + y) * WW * 96;
#pragma unroll
    for (int mt = 0; mt < 3; mt++)
#pragma unroll
        for (int nt = 0; nt < 3; nt++) {
            const int x0 = wm * 48 + mt * 16 + (lane >> 2);
            const int i0 = wn * 24 + nt * 8 + (lane & 3) * 2;
            *(bf162*)&Eb[(size_t)x0 * 96 + i0] = bf162{
                __float2bfloat16(acc[mt][nt][0]), __float2bfloat16(acc[mt][nt][1])};
            *(bf162*)&Eb[(size_t)(x0 + 8) * 96 + i0] = bf162{
                __float2bfloat16(acc[mt][nt][2]), __float2bfloat16(acc[mt][nt][3])};
        }
}

// ---------------------------------------------------------------------------
// Kernel 3 (fused): per (x, bh): col logits (mma, SMEM) + softmax(192)
//   with direct prob emission + column output (mma) -> d_O (bf16).
// SMEM phases:
//   P1: t@0, f@13824 (27648) | Ec f32 [96][100] @38400 (38400)
//   P2: Er f32 [96][100] @0 (converted from bf16 gmem) | g bf16 [96][72] @76800
//   P3: Acol bf16 [96] pitch 200 bf16 (400 B) @0 — in-place over Er rows.
// total 90624 B
// ---------------------------------------------------------------------------
#define EC_OFF 38400
#define G_OFF  76800
#define PAC 200   // Ac pitch in bf16 (= Er row pitch of 400 B)

__global__ void __launch_bounds__(256) fusedcol_kernel()
{
    extern __shared__ __align__(16) char smem[];
    const uint32_t sb = smem_u32(smem);

    const int x = blockIdx.x, bh = blockIdx.y, tid = threadIdx.x;
    const int lane = tid & 31, warp = tid >> 5;
    const int wm = warp >> 2, wn = warp & 3;

    // P1 load: t/f columns (row stride WW*DD)
    {
        const size_t off = ((size_t)bh * HW + x) * DD;
        const bf16* srcs[2] = {d_tb + off, d_fb + off};
#pragma unroll
        for (int a = 0; a < 2; a++)
#pragma unroll
            for (int k = 0; k < 3; k++) {
                int idx = tid + k * 256;
                int row = idx >> 3, c = (idx & 7) * 8;
                *(uint4*)(smem + a * ABUF + (row * PBF + c) * 2) =
                    *(const uint4*)(srcs[a] + (size_t)row * (WW * DD) + c);
            }
    }
    __syncthreads();

    // column logits -> Ec with diagonal mask
    {
        float acc[3][3][4];
#pragma unroll
        for (int mt = 0; mt < 3; mt++)
#pragma unroll
            for (int nt = 0; nt < 3; nt++)
#pragma unroll
                for (int k = 0; k < 4; k++) acc[mt][nt][k] = 0.f;

        logits_mma(sb, 0, ABUF, lane, wm, wn, acc);

        float (*Ec)[100] = (float(*)[100])(smem + EC_OFF);
#pragma unroll
        for (int mt = 0; mt < 3; mt++)
#pragma unroll
            for (int nt = 0; nt < 3; nt++) {
                const int y0 = wm * 48 + mt * 16 + (lane >> 2);
                const int i0 = wn * 24 + nt * 8 + (lane & 3) * 2;
                Ec[y0][i0]     = (i0     == y0)     ? -INFINITY : acc[mt][nt][0];
                Ec[y0][i0 + 1] = (i0 + 1 == y0)     ? -INFINITY : acc[mt][nt][1];
                Ec[y0 + 8][i0]     = (i0     == y0 + 8) ? -INFINITY : acc[mt][nt][2];
                Ec[y0 + 8][i0 + 1] = (i0 + 1 == y0 + 8) ? -INFINITY : acc[mt][nt][3];
            }
    }
    __syncthreads();   // t/f reads done, Ec complete

    // P2 loads: Er slice (bf16 -> fp32 smem) + g column
    {
        float (*Er)[100] = (float(*)[100])smem;
        const bf16* eb = d_Er + (size_t)bh * HW * 96 + (size_t)x * 96;
        for (int idx = tid; idx < 96 * 12; idx += 256) {
            int r = idx / 12, c8 = idx % 12;
            uint4 raw = *(const uint4*)(eb + (size_t)r * (WW * 96) + c8 * 8);
            const bf162* pr = (const bf162*)&raw;
#pragma unroll
            for (int j = 0; j < 4; j++) {
                float2 f = __bfloat1622float2(pr[j]);
                Er[r][c8 * 8 + j * 2]     = f.x;
                Er[r][c8 * 8 + j * 2 + 1] = f.y;
            }
        }
        const bf16* gsrc = d_gb + ((size_t)bh * HW + x) * DD;
#pragma unroll
        for (int k = 0; k < 3; k++) {
            int idx = tid + k * 256;
            int row = idx >> 3, c = (idx & 7) * 8;
            *(uint4*)(smem + G_OFF + (row * PBF + c) * 2) =
                *(const uint4*)(gsrc + (size_t)row * (WW * DD) + c);
        }
    }
    __syncthreads();

    // softmax over concat(Er, Ec) — warp per row; emits probs directly
    {
        float (*Er)[100] = (float(*)[100])smem;
        float (*Ec)[100] = (float(*)[100])(smem + EC_OFF);
        bf16* Ac = (bf16*)smem;
#pragma unroll 1
        for (int rr = 0; rr < 12; rr++) {
            const int r = warp * 12 + rr;
            float vr[3], vc[3];
#pragma unroll
            for (int k = 0; k < 3; k++) { vr[k] = Er[r][lane + k * 32]; vc[k] = Ec[r][lane + k * 32]; }
            float m = -INFINITY;
#pragma unroll
            for (int k = 0; k < 3; k++) m = fmaxf(m, fmaxf(vr[k], vc[k]));
#pragma unroll
            for (int off = 16; off; off >>= 1) m = fmaxf(m, __shfl_xor_sync(0xffffffffu, m, off));
            float s = 0.f;
#pragma unroll
            for (int k = 0; k < 3; k++) {
                vr[k] = __expf(vr[k] - m); vc[k] = __expf(vc[k] - m);
                s += vr[k] + vc[k];
            }
#pragma unroll
            for (int off = 16; off; off >>= 1) s += __shfl_xor_sync(0xffffffffu, s, off);
            const float inv = 1.f / s;
            bf16* arow = d_Ar + ((size_t)(bh * HH + r) * WW + x) * 96;
            bf16* acrow = Ac + r * PAC;
#pragma unroll
            for (int k = 0; k < 3; k++) {
                arow[lane + k * 32]  = __float2bfloat16(vr[k] * inv);
                acrow[lane + k * 32] = __float2bfloat16(vc[k] * inv);
            }
        }
    }
    __syncthreads();

    // column output mma -> d_O (bf16)
    {
        float acc[3][2][4];
#pragma unroll
        for (int mt = 0; mt < 3; mt++)
#pragma unroll
            for (int nt = 0; nt < 2; nt++)
#pragma unroll
                for (int k = 0; k < 4; k++) acc[mt][nt][k] = 0.f;

        probs_mma<PAC>(sb, 0, G_OFF, lane, wm, wn, acc);

#pragma unroll
        for (int mt = 0; mt < 3; mt++)
#pragma unroll
            for (int nt = 0; nt < 2; nt++) {
                const int yv = wm * 48 + mt * 16 + (lane >> 2);
                const int d0 = wn * 16 + nt * 8 + (lane & 3) * 2;
                bf16* ob = d_O + ((size_t)(bh * HH + yv) * WW + x) * DD + d0;
                *(bf162*)ob = bf162{
                    __float2bfloat16(acc[mt][nt][0]), __float2bfloat16(acc[mt][nt][1])};
                *(bf162*)(ob + (size_t)8 * WW * DD) = bf162{
                    __float2bfloat16(acc[mt][nt][2]), __float2bfloat16(acc[mt][nt][3])};
            }
    }
}

// ---------------------------------------------------------------------------
// Kernel 4: row output (mma) + combine + residual. Block (y, bh).
// ---------------------------------------------------------------------------
__global__ void __launch_bounds__(256) rowout_kernel(
    const float* __restrict__ v, const float* __restrict__ gamma,
    float* __restrict__ out)
{
    __shared__ __align__(16) bf16 Asm[96][PA];
    __shared__ __align__(16) bf16 gsm[96][PBF];

    const int y = blockIdx.x, bh = blockIdx.y, tid = threadIdx.x;
    const int lane = tid & 31, warp = tid >> 5;
    const int wm = warp >> 2, wn = warp & 3;

    const bf16* ab = d_Ar + ((size_t)bh * HH + y) * WW * 96;
    for (int idx = tid; idx < 96 * 12; idx += 256) {
        int row = idx / 12, c8 = idx % 12;
        *(uint4*)&Asm[row][c8 * 8] = *(const uint4*)(ab + (size_t)row * 96 + c8 * 8);
    }
    const bf16* gb = d_gb + ((size_t)bh * HH + y) * WW * DD;
#pragma unroll
    for (int k = 0; k < 3; k++) {
        int idx = tid + k * 256;
        int row = idx >> 3, c = (idx & 7) * 8;
        *(uint4*)&gsm[row][c] = *(const uint4*)(gb + (size_t)idx * 8);
    }
    __syncthreads();

    float acc[3][2][4];
#pragma unroll
    for (int mt = 0; mt < 3; mt++)
#pragma unroll
        for (int nt = 0; nt < 2; nt++)
#pragma unroll
            for (int k = 0; k < 4; k++) acc[mt][nt][k] = 0.f;

    const uint32_t sbA = smem_u32(Asm);
    const uint32_t sbG = smem_u32(gsm);
    probs_mma<PA>(sbA, 0, sbG - sbA, lane, wm, wn, acc);

    const float gam = gamma[0];
    const int b = bh >> 3, h = bh & 7;
    const bf16* colp = d_O + ((size_t)bh * HH + y) * WW * DD;

#pragma unroll
    for (int mt = 0; mt < 3; mt++)
#pragma unroll
        for (int nt = 0; nt < 2; nt++) {
            const int x0 = wm * 48 + mt * 16 + (lane >> 2);
            const int d0 = wn * 16 + nt * 8 + (lane & 3) * 2;
#pragma unroll
            for (int rh = 0; rh < 2; rh++) {
                const int xx = x0 + rh * 8;
                float2 cp = __bfloat1622float2(
                    *(const bf162*)(colp + (size_t)xx * DD + d0));
                float s0 = acc[mt][nt][rh * 2]     + cp.x;
                float s1 = acc[mt][nt][rh * 2 + 1] + cp.y;
                size_t oa0 = (((size_t)(b * CC + h * 64 + d0)) * HH + y) * WW + xx;
                size_t oa1 = oa0 + (size_t)HW;
                out[oa0] = gam * s0 + v[oa0];
                out[oa1] = gam * s1 + v[oa1];
            }
        }
}

// ---------------------------------------------------------------------------
extern "C" void kernel_launch(void* const* d_in, const int* in_sizes, int n_in,
                              void* d_out, int out_size)
{
    const float* q     = (const float*)d_in[0];
    const float* v     = (const float*)d_in[1];
    const float* Wq    = (const float*)d_in[2];
    const float* bq    = (const float*)d_in[3];
    const float* Wk    = (const float*)d_in[4];
    const float* bk    = (const float*)d_in[5];
    const float* Wv    = (const float*)d_in[6];
    const float* bv    = (const float*)d_in[7];
    const float* gamma = (const float*)d_in[8];
    float* out = (float*)d_out;

    static bf16 *pAq = nullptr, *pAv, *pW, *pT, *pF, *pG;
    static cudaStream_t s2;
    static cudaEvent_t evFork, evA, evW, evJoin;
    if (!pAq) {
        cudaGetSymbolAddress((void**)&pAq, d_Aq);
        cudaGetSymbolAddress((void**)&pAv, d_Av);
        cudaGetSymbolAddress((void**)&pW,  d_W);
        cudaGetSymbolAddress((void**)&pT,  d_tb);
        cudaGetSymbolAddress((void**)&pF,  d_fb);
        cudaGetSymbolAddress((void**)&pG,  d_gb);
        cudaStreamCreateWithFlags(&s2, cudaStreamNonBlocking);
        cudaEventCreateWithFlags(&evFork, cudaEventDisableTiming);
        cudaEventCreateWithFlags(&evA,    cudaEventDisableTiming);
        cudaEventCreateWithFlags(&evW,    cudaEventDisableTiming);
        cudaEventCreateWithFlags(&evJoin, cudaEventDisableTiming);
    }

    const int smConv = NSTG * STGB;  // 81920
    const int smE    = 2 * ABUF;     // 27648
    const int smF    = G_OFF + ABUF; // 90624
    static bool attrs_set = false;
    if (!attrs_set) {
        cudaFuncSetAttribute(conv_wmma_kernel, cudaFuncAttributeMaxDynamicSharedMemorySize, smConv);
        cudaFuncSetAttribute(erow_kernel,      cudaFuncAttributeMaxDynamicSharedMemorySize, smE);
        cudaFuncSetAttribute(fusedcol_kernel,  cudaFuncAttributeMaxDynamicSharedMemorySize, smF);
        attrs_set = true;
    }

    // Fork s2 from the capture stream FIRST (capture-legality requirement)
    cudaEventRecord(evFork, 0);
    cudaStreamWaitEvent(s2, evFork, 0);

    // Prepasses: toW on s2 concurrent with toA on main stream
    dim3 wGrid((CC * CC + 255) / 256, 3);
    toW_kernel<<<wGrid, 256, 0, s2>>>(Wq, Wk, Wv, pW);
    cudaEventRecord(evW, s2);

    dim3 spGrid(HW / 32, CC / 32, 2 * BB);
    toA_kernel<<<spGrid, 256>>>(q, v, pAq, pAv);
    cudaEventRecord(evA, 0);

    // conv-g on s2 (needs toW [same stream] + toA)
    cudaStreamWaitEvent(s2, evA, 0);
    dim3 cg(MTOT / 128, CC / 128);   // 288 x 4
    conv_wmma_kernel<<<cg, 256, smConv, s2>>>(pAv, pW + 2 * CC * CC, bv, 1.0f, pG,
                                              bv, 1.0f, pG);

    // fused t+f conv on main stream (needs toA [same stream] + toW)
    cudaStreamWaitEvent(0, evW, 0);
    dim3 ctf(MTOT / 128, 2 * CC / 128);  // 288 x 8 over [Wq;Wk]
    conv_wmma_kernel<<<ctf, 256, smConv>>>(pAq, pW, bq, SCALING, pT,
                                           bk, 1.0f, pF);

    // erow (needs t, f) overlaps tail of conv-g
    dim3 attnGrid(96, BHD);
    erow_kernel<<<attnGrid, 256, smE>>>();

    cudaEventRecord(evJoin, s2);
    cudaStreamWaitEvent(0, evJoin, 0);

    // Remaining attention
    fusedcol_kernel<<<attnGrid, 256, smF>>>();
    rowout_kernel<<<attnGrid, 256>>>(v, gamma, out);
}

// round 16
// speedup vs baseline: 1.0703x; 1.0215x over previous
#include <cuda_runtime.h>
#include <cuda_bf16.h>
#include <math.h>
#include <cstdint>

#define BB 4
#define NH 8
#define BHD 32
#define HH 96
#define WW 96
#define CC 512
#define DD 64
#define HW 9216
#define MTOT (BB * HW)      // 36864
#define SCALING 0.125f

typedef __nv_bfloat16 bf16;
typedef __nv_bfloat162 bf162;

// ---------------------------------------------------------------------------
// Device-global scratch
// ---------------------------------------------------------------------------
__device__ bf16 d_Er[(size_t)BHD * HW * 96];   // row logits (bf16)
__device__ bf16 d_Ar[(size_t)BHD * HW * 96];   // row probs (bf16)
__device__ bf16 d_O [(size_t)BHD * HW * DD];   // column partial (bf16)
__device__ bf16 d_tb[(size_t)BHD * HW * DD];
__device__ bf16 d_fb[(size_t)BHD * HW * DD];
__device__ bf16 d_gb[(size_t)BHD * HW * DD];
__device__ bf16 d_Aq[(size_t)MTOT * CC];
__device__ bf16 d_Av[(size_t)MTOT * CC];
__device__ bf16 d_W [3 * CC * CC];

// ---------------------------------------------------------------------------
// Helpers (generic PTX: sm_80+ features only)
// ---------------------------------------------------------------------------
__device__ __forceinline__ uint32_t smem_u32(const void* p) {
    uint32_t a;
    asm("{ .reg .u64 t; cvta.to.shared.u64 t, %1; cvt.u32.u64 %0, t; }" : "=r"(a) : "l"(p));
    return a;
}
__device__ __forceinline__ void cpa16(uint32_t d, const void* s) {
    asm volatile("cp.async.ca.shared.global [%0], [%1], 16;" :: "r"(d), "l"(s));
}
__device__ __forceinline__ void ldmx4(uint32_t* r, uint32_t addr) {
    asm volatile("ldmatrix.sync.aligned.m8n8.x4.shared.b16 {%0,%1,%2,%3}, [%4];"
        : "=r"(r[0]), "=r"(r[1]), "=r"(r[2]), "=r"(r[3]) : "r"(addr));
}
__device__ __forceinline__ void ldmxt4(uint32_t* r, uint32_t addr) {
    asm volatile("ldmatrix.sync.aligned.m8n8.x4.trans.shared.b16 {%0,%1,%2,%3}, [%4];"
        : "=r"(r[0]), "=r"(r[1]), "=r"(r[2]), "=r"(r[3]) : "r"(addr));
}
__device__ __forceinline__ void ldmx2(uint32_t* r, uint32_t addr) {
    asm volatile("ldmatrix.sync.aligned.m8n8.x2.shared.b16 {%0,%1}, [%2];"
        : "=r"(r[0]), "=r"(r[1]) : "r"(addr));
}
__device__ __forceinline__ void mma16816(float* c, const uint32_t* a,
                                         uint32_t b0, uint32_t b1) {
    asm volatile(
        "mma.sync.aligned.m16n8k16.row.col.f32.bf16.bf16.f32 "
        "{%0,%1,%2,%3}, {%4,%5,%6,%7}, {%8,%9}, {%0,%1,%2,%3};"
        : "+f"(c[0]), "+f"(c[1]), "+f"(c[2]), "+f"(c[3])
        : "r"(a[0]), "r"(a[1]), "r"(a[2]), "r"(a[3]), "r"(b0), "r"(b1));
}

// ---------------------------------------------------------------------------
// Prepass A: transpose + bf16 convert  X[b][c][px] -> A [m][c]  (one tensor)
// ---------------------------------------------------------------------------
__global__ void __launch_bounds__(256) toA_kernel(
    const float* __restrict__ X, bf16* __restrict__ dst)
{
    __shared__ float tile[32][33];
    const int t   = threadIdx.x;
    const int px0 = blockIdx.x * 32;
    const int c0  = blockIdx.y * 32;
    const int b   = blockIdx.z;

#pragma unroll
    for (int r = 0; r < 4; r++) {
        int ci = (t >> 5) + r * 8, pj = t & 31;
        tile[ci][pj] = X[((size_t)b * CC + c0 + ci) * HW + px0 + pj];
    }
    __syncthreads();
#pragma unroll
    for (int r = 0; r < 4; r++) {
        int pj = (t >> 5) + r * 8, ci = t & 31;
        dst[((size_t)b * HW + px0 + pj) * CC + c0 + ci] = __float2bfloat16(tile[ci][pj]);
    }
}

__global__ void __launch_bounds__(256) toW_kernel(
    const float* __restrict__ W0, const float* __restrict__ W1,
    const float* __restrict__ W2, bf16* __restrict__ dst)
{
    const int w = blockIdx.y;
    const float* W = (w == 0) ? W0 : (w == 1) ? W1 : W2;
    int i = blockIdx.x * 256 + threadIdx.x;
    if (i < CC * CC) dst[(size_t)w * CC * CC + i] = __float2bfloat16(W[i]);
}

// ---------------------------------------------------------------------------
// Conv GEMM on mma.sync, cp.async 4-stage pipeline. 128x128 tile, K chunk 32.
// (8 warps, warp tile 32x64, 2 CTAs/SM.)  Fused double-output over [W1;W2].
// ---------------------------------------------------------------------------
#define KPAD 40
#define AOFF 0
#define BOFF (128 * KPAD * 2)       // 10240
#define STGB (2 * 128 * KPAD * 2)   // 20480
#define NSTG 4

__global__ void __launch_bounds__(256) conv_wmma_kernel(
    const bf16* __restrict__ A, const bf16* __restrict__ B,
    const float* __restrict__ bias, float scale, bf16* __restrict__ dst,
    const float* __restrict__ bias2, float scale2, bf16* __restrict__ dst2)
{
    extern __shared__ __align__(16) bf16 cs[];
    const uint32_t sb = smem_u32(cs);

    const int tid  = threadIdx.x;
    const int lane = tid & 31;
    const int warp = tid >> 5;
    const int wm   = warp & 3;
    const int wn   = warp >> 2;

    const int M0 = blockIdx.x * 128;
    const int o0 = blockIdx.y * 128;

    const int side = (o0 >= CC);
    const float* bb = side ? bias2 : bias;
    bf16* dd        = side ? dst2  : dst;
    const float sc  = side ? scale2 : scale;
    const int oo0   = o0 - side * CC;

    const int crow = tid >> 2, cseg = tid & 3;
    const bf16* pA = A + (size_t)(M0 + crow) * CC + cseg * 8;
    const bf16* pB = B + (size_t)(o0 + crow) * CC + cseg * 8;
    const uint32_t sdst = (crow * KPAD + cseg * 8) * 2;
    const uint32_t rstep = 64 * KPAD * 2;

    float acc[2][8][4];
#pragma unroll
    for (int mi = 0; mi < 2; mi++)
#pragma unroll
        for (int nf = 0; nf < 8; nf++)
#pragma unroll
            for (int k = 0; k < 4; k++) acc[mi][nf][k] = 0.f;

    const int lrow = lane & 15;
    const int lsel = (lane >> 4) * 8;

#pragma unroll
    for (int p = 0; p < 3; p++) {
        uint32_t so = sb + p * STGB + sdst;
#pragma unroll
        for (int r = 0; r < 2; r++) {
            const size_t go = (size_t)r * 64 * CC + p * 32;
            cpa16(so + AOFF + r * rstep, pA + go);
            cpa16(so + BOFF + r * rstep, pB + go);
        }
        asm volatile("cp.async.commit_group;");
    }

    for (int ch = 0; ch < 16; ch++) {
        if (ch + 3 < 16) {
            uint32_t so = sb + ((ch + 3) % NSTG) * STGB + sdst;
#pragma unroll
            for (int r = 0; r < 2; r++) {
                const size_t go = (size_t)r * 64 * CC + (ch + 3) * 32;
                cpa16(so + AOFF + r * rstep, pA + go);
                cpa16(so + BOFF + r * rstep, pB + go);
            }
            asm volatile("cp.async.commit_group;");
            asm volatile("cp.async.wait_group 3;");
        } else if (ch + 2 < 16) {
            asm volatile("cp.async.wait_group 2;");
        } else if (ch + 1 < 16) {
            asm volatile("cp.async.wait_group 1;");
        } else {
            asm volatile("cp.async.wait_group 0;");
        }
        __syncthreads();

        const uint32_t stb = sb + (ch % NSTG) * STGB;
#pragma unroll
        for (int ks = 0; ks < 2; ks++) {
            const int kc = ks * 16 + lsel;
            uint32_t a[2][4];
#pragma unroll
            for (int mi = 0; mi < 2; mi++)
                ldmx4(a[mi], stb + AOFF + ((wm * 32 + mi * 16 + lrow) * KPAD + kc) * 2);
#pragma unroll
            for (int np = 0; np < 4; np++) {
                uint32_t b[4];
                ldmx4(b, stb + BOFF + ((wn * 64 + np * 16 + lrow) * KPAD + kc) * 2);
#pragma unroll
                for (int mi = 0; mi < 2; mi++)
#pragma unroll
                    for (int hf = 0; hf < 2; hf++)
                        mma16816(acc[mi][np * 2 + hf], a[mi], b[hf], b[2 + hf]);
            }
        }
        __syncthreads();
    }

#pragma unroll
    for (int mi = 0; mi < 2; mi++) {
        const int m  = M0 + wm * 32 + mi * 16 + (lane >> 2);
        const int b  = m / HW;
        const int pp = m % HW;
#pragma unroll
        for (int nf = 0; nf < 8; nf++) {
            const int o = oo0 + wn * 64 + nf * 8 + (lane & 3) * 2;
            const int h = o >> 6, d = o & 63;
            const float b0 = bb[o], b1 = bb[o + 1];
            size_t i0 = ((size_t)(b * NH + h) * HW + pp) * DD + d;
            size_t i1 = i0 + (size_t)8 * DD;
            *(bf162*)(dd + i0) = bf162{
                __float2bfloat16((acc[mi][nf][0] + b0) * sc),
                __float2bfloat16((acc[mi][nf][1] + b1) * sc)};
            *(bf162*)(dd + i1) = bf162{
                __float2bfloat16((acc[mi][nf][2] + b0) * sc),
                __float2bfloat16((acc[mi][nf][3] + b1) * sc)};
        }
    }
}

// ---------------------------------------------------------------------------
// Logits mma: C[96][96] = A[96][64] * B[96][64]^T, bf16, pitch 72.
// ---------------------------------------------------------------------------
#define PBF 72
#define ABUF 13824   // 96*72*2

__device__ __forceinline__ void logits_mma(
    uint32_t sb, uint32_t aOff, uint32_t bOff, int lane, int wm, int wn,
    float acc[3][3][4])
{
    const int l15 = lane & 15;
#pragma unroll
    for (int ks = 0; ks < 4; ks++) {
        const int kc = ks * 16;
        uint32_t a[3][4];
#pragma unroll
        for (int mt = 0; mt < 3; mt++)
            ldmx4(a[mt], sb + aOff +
                ((wm * 48 + mt * 16 + l15) * PBF + kc + (lane >> 4) * 8) * 2);
#pragma unroll
        for (int nt = 0; nt < 3; nt++) {
            uint32_t b[2];
            ldmx2(b, sb + bOff +
                ((wn * 24 + nt * 8 + (l15 & 7)) * PBF + kc + ((l15 >> 3) & 1) * 8) * 2);
#pragma unroll
            for (int mt = 0; mt < 3; mt++)
                mma16816(acc[mt][nt], a[mt], b[0], b[1]);
        }
    }
}

// Output mma: C[96][64] = A[96][96](pitch APITCH bf16) * B[96][64](pitch 72, trans)
#define PA 104

template <int APITCH>
__device__ __forceinline__ void probs_mma(
    uint32_t sb, uint32_t aOff, uint32_t gOff, int lane, int wm, int wn,
    float acc[3][2][4])
{
    const int l15 = lane & 15;
#pragma unroll
    for (int ks = 0; ks < 6; ks++) {
        const int kc = ks * 16;
        uint32_t a[3][4];
#pragma unroll
        for (int mt = 0; mt < 3; mt++)
            ldmx4(a[mt], sb + aOff +
                ((wm * 48 + mt * 16 + l15) * APITCH + kc + (lane >> 4) * 8) * 2);
        uint32_t bt[4];
        ldmxt4(bt, sb + gOff + ((kc + l15) * PBF + wn * 16 + (lane >> 4) * 8) * 2);
#pragma unroll
        for (int mt = 0; mt < 3; mt++) {
            mma16816(acc[mt][0], a[mt], bt[0], bt[1]);
            mma16816(acc[mt][1], a[mt], bt[2], bt[3]);
        }
    }
}

// ---------------------------------------------------------------------------
// Kernel 2: row logits -> d_Er (bf16). Block (y, bh-bh0).
// ---------------------------------------------------------------------------
__global__ void __launch_bounds__(256) erow_kernel(int bh0)
{
    extern __shared__ __align__(16) char smem[];
    const uint32_t sb = smem_u32(smem);

    const int y = blockIdx.x, bh = blockIdx.y + bh0, tid = threadIdx.x;
    const int lane = tid & 31, warp = tid >> 5;

    const size_t off = ((size_t)bh * HW + y * 96) * DD;
    const bf16* srcs[2] = {d_tb + off, d_fb + off};
#pragma unroll
    for (int a = 0; a < 2; a++)
#pragma unroll
        for (int k = 0; k < 3; k++) {
            int idx = tid + k * 256;
            int row = idx >> 3, c = (idx & 7) * 8;
            *(uint4*)(smem + a * ABUF + (row * PBF + c) * 2) =
                *(const uint4*)(srcs[a] + (size_t)idx * 8);
        }
    __syncthreads();

    float acc[3][3][4];
#pragma unroll
    for (int mt = 0; mt < 3; mt++)
#pragma unroll
        for (int nt = 0; nt < 3; nt++)
#pragma unroll
            for (int k = 0; k < 4; k++) acc[mt][nt][k] = 0.f;

    const int wm = warp >> 2, wn = warp & 3;
    logits_mma(sb, 0, ABUF, lane, wm, wn, acc);

    bf16* Eb = d_Er + ((size_t)bh * HH + y) * WW * 96;
#pragma unroll
    for (int mt = 0; mt < 3; mt++)
#pragma unroll
        for (int nt = 0; nt < 3; nt++) {
            const int x0 = wm * 48 + mt * 16 + (lane >> 2);
            const int i0 = wn * 24 + nt * 8 + (lane & 3) * 2;
            *(bf162*)&Eb[(size_t)x0 * 96 + i0] = bf162{
                __float2bfloat16(acc[mt][nt][0]), __float2bfloat16(acc[mt][nt][1])};
            *(bf162*)&Eb[(size_t)(x0 + 8) * 96 + i0] = bf162{
                __float2bfloat16(acc[mt][nt][2]), __float2bfloat16(acc[mt][nt][3])};
        }
}

// ---------------------------------------------------------------------------
// Kernel 3 (fused): per (x, bh-bh0): col logits + softmax(192) + prob emission
//   + column output (mma) -> d_O (bf16).
// ---------------------------------------------------------------------------
#define EC_OFF 38400
#define G_OFF  76800
#define PAC 200

__global__ void __launch_bounds__(256) fusedcol_kernel(int bh0)
{
    extern __shared__ __align__(16) char smem[];
    const uint32_t sb = smem_u32(smem);

    const int x = blockIdx.x, bh = blockIdx.y + bh0, tid = threadIdx.x;
    const int lane = tid & 31, warp = tid >> 5;
    const int wm = warp >> 2, wn = warp & 3;

    // P1 load: t/f columns (row stride WW*DD)
    {
        const size_t off = ((size_t)bh * HW + x) * DD;
        const bf16* srcs[2] = {d_tb + off, d_fb + off};
#pragma unroll
        for (int a = 0; a < 2; a++)
#pragma unroll
            for (int k = 0; k < 3; k++) {
                int idx = tid + k * 256;
                int row = idx >> 3, c = (idx & 7) * 8;
                *(uint4*)(smem + a * ABUF + (row * PBF + c) * 2) =
                    *(const uint4*)(srcs[a] + (size_t)row * (WW * DD) + c);
            }
    }
    __syncthreads();

    // column logits -> Ec with diagonal mask
    {
        float acc[3][3][4];
#pragma unroll
        for (int mt = 0; mt < 3; mt++)
#pragma unroll
            for (int nt = 0; nt < 3; nt++)
#pragma unroll
                for (int k = 0; k < 4; k++) acc[mt][nt][k] = 0.f;

        logits_mma(sb, 0, ABUF, lane, wm, wn, acc);

        float (*Ec)[100] = (float(*)[100])(smem + EC_OFF);
#pragma unroll
        for (int mt = 0; mt < 3; mt++)
#pragma unroll
            for (int nt = 0; nt < 3; nt++) {
                const int y0 = wm * 48 + mt * 16 + (lane >> 2);
                const int i0 = wn * 24 + nt * 8 + (lane & 3) * 2;
                Ec[y0][i0]     = (i0     == y0)     ? -INFINITY : acc[mt][nt][0];
                Ec[y0][i0 + 1] = (i0 + 1 == y0)     ? -INFINITY : acc[mt][nt][1];
                Ec[y0 + 8][i0]     = (i0     == y0 + 8) ? -INFINITY : acc[mt][nt][2];
                Ec[y0 + 8][i0 + 1] = (i0 + 1 == y0 + 8) ? -INFINITY : acc[mt][nt][3];
            }
    }
    __syncthreads();

    // P2 loads: Er slice (bf16 -> fp32 smem) + g column
    {
        float (*Er)[100] = (float(*)[100])smem;
        const bf16* eb = d_Er + (size_t)bh * HW * 96 + (size_t)x * 96;
        for (int idx = tid; idx < 96 * 12; idx += 256) {
            int r = idx / 12, c8 = idx % 12;
            uint4 raw = *(const uint4*)(eb + (size_t)r * (WW * 96) + c8 * 8);
            const bf162* pr = (const bf162*)&raw;
#pragma unroll
            for (int j = 0; j < 4; j++) {
                float2 f = __bfloat1622float2(pr[j]);
                Er[r][c8 * 8 + j * 2]     = f.x;
                Er[r][c8 * 8 + j * 2 + 1] = f.y;
            }
        }
        const bf16* gsrc = d_gb + ((size_t)bh * HW + x) * DD;
#pragma unroll
        for (int k = 0; k < 3; k++) {
            int idx = tid + k * 256;
            int row = idx >> 3, c = (idx & 7) * 8;
            *(uint4*)(smem + G_OFF + (row * PBF + c) * 2) =
                *(const uint4*)(gsrc + (size_t)row * (WW * DD) + c);
        }
    }
    __syncthreads();

    // softmax over concat(Er, Ec) — warp per row; emits probs directly
    {
        float (*Er)[100] = (float(*)[100])smem;
        float (*Ec)[100] = (float(*)[100])(smem + EC_OFF);
        bf16* Ac = (bf16*)smem;
#pragma unroll 1
        for (int rr = 0; rr < 12; rr++) {
            const int r = warp * 12 + rr;
            float vr[3], vc[3];
#pragma unroll
            for (int k = 0; k < 3; k++) { vr[k] = Er[r][lane + k * 32]; vc[k] = Ec[r][lane + k * 32]; }
            float m = -INFINITY;
#pragma unroll
            for (int k = 0; k < 3; k++) m = fmaxf(m, fmaxf(vr[k], vc[k]));
#pragma unroll
            for (int off = 16; off; off >>= 1) m = fmaxf(m, __shfl_xor_sync(0xffffffffu, m, off));
            float s = 0.f;
#pragma unroll
            for (int k = 0; k < 3; k++) {
                vr[k] = __expf(vr[k] - m); vc[k] = __expf(vc[k] - m);
                s += vr[k] + vc[k];
            }
#pragma unroll
            for (int off = 16; off; off >>= 1) s += __shfl_xor_sync(0xffffffffu, s, off);
            const float inv = 1.f / s;
            bf16* arow = d_Ar + ((size_t)(bh * HH + r) * WW + x) * 96;
            bf16* acrow = Ac + r * PAC;
#pragma unroll
            for (int k = 0; k < 3; k++) {
                arow[lane + k * 32]  = __float2bfloat16(vr[k] * inv);
                acrow[lane + k * 32] = __float2bfloat16(vc[k] * inv);
            }
        }
    }
    __syncthreads();

    // column output mma -> d_O (bf16)
    {
        float acc[3][2][4];
#pragma unroll
        for (int mt = 0; mt < 3; mt++)
#pragma unroll
            for (int nt = 0; nt < 2; nt++)
#pragma unroll
                for (int k = 0; k < 4; k++) acc[mt][nt][k] = 0.f;

        probs_mma<PAC>(sb, 0, G_OFF, lane, wm, wn, acc);

#pragma unroll
        for (int mt = 0; mt < 3; mt++)
#pragma unroll
            for (int nt = 0; nt < 2; nt++) {
                const int yv = wm * 48 + mt * 16 + (lane >> 2);
                const int d0 = wn * 16 + nt * 8 + (lane & 3) * 2;
                bf16* ob = d_O + ((size_t)(bh * HH + yv) * WW + x) * DD + d0;
                *(bf162*)ob = bf162{
                    __float2bfloat16(acc[mt][nt][0]), __float2bfloat16(acc[mt][nt][1])};
                *(bf162*)(ob + (size_t)8 * WW * DD) = bf162{
                    __float2bfloat16(acc[mt][nt][2]), __float2bfloat16(acc[mt][nt][3])};
            }
    }
}

// ---------------------------------------------------------------------------
// Kernel 4: row output (mma) + combine + residual. Block (y, bh-bh0).
// ---------------------------------------------------------------------------
__global__ void __launch_bounds__(256) rowout_kernel(
    const float* __restrict__ v, const float* __restrict__ gamma,
    float* __restrict__ out, int bh0)
{
    __shared__ __align__(16) bf16 Asm[96][PA];
    __shared__ __align__(16) bf16 gsm[96][PBF];

    const int y = blockIdx.x, bh = blockIdx.y + bh0, tid = threadIdx.x;
    const int lane = tid & 31, warp = tid >> 5;
    const int wm = warp >> 2, wn = warp & 3;

    const bf16* ab = d_Ar + ((size_t)bh * HH + y) * WW * 96;
    for (int idx = tid; idx < 96 * 12; idx += 256) {
        int row = idx / 12, c8 = idx % 12;
        *(uint4*)&Asm[row][c8 * 8] = *(const uint4*)(ab + (size_t)row * 96 + c8 * 8);
    }
    const bf16* gb = d_gb + ((size_t)bh * HH + y) * WW * DD;
#pragma unroll
    for (int k = 0; k < 3; k++) {
        int idx = tid + k * 256;
        int row = idx >> 3, c = (idx & 7) * 8;
        *(uint4*)&gsm[row][c] = *(const uint4*)(gb + (size_t)idx * 8);
    }
    __syncthreads();

    float acc[3][2][4];
#pragma unroll
    for (int mt = 0; mt < 3; mt++)
#pragma unroll
        for (int nt = 0; nt < 2; nt++)
#pragma unroll
            for (int k = 0; k < 4; k++) acc[mt][nt][k] = 0.f;

    const uint32_t sbA = smem_u32(Asm);
    const uint32_t sbG = smem_u32(gsm);
    probs_mma<PA>(sbA, 0, sbG - sbA, lane, wm, wn, acc);

    const float gam = gamma[0];
    const int b = bh >> 3, h = bh & 7;
    const bf16* colp = d_O + ((size_t)bh * HH + y) * WW * DD;

#pragma unroll
    for (int mt = 0; mt < 3; mt++)
#pragma unroll
        for (int nt = 0; nt < 2; nt++) {
            const int x0 = wm * 48 + mt * 16 + (lane >> 2);
            const int d0 = wn * 16 + nt * 8 + (lane & 3) * 2;
#pragma unroll
            for (int rh = 0; rh < 2; rh++) {
                const int xx = x0 + rh * 8;
                float2 cp = __bfloat1622float2(
                    *(const bf162*)(colp + (size_t)xx * DD + d0));
                float s0 = acc[mt][nt][rh * 2]     + cp.x;
                float s1 = acc[mt][nt][rh * 2 + 1] + cp.y;
                size_t oa0 = (((size_t)(b * CC + h * 64 + d0)) * HH + y) * WW + xx;
                size_t oa1 = oa0 + (size_t)HW;
                out[oa0] = gam * s0 + v[oa0];
                out[oa1] = gam * s1 + v[oa1];
            }
        }
}

// ---------------------------------------------------------------------------
extern "C" void kernel_launch(void* const* d_in, const int* in_sizes, int n_in,
                              void* d_out, int out_size)
{
    const float* q     = (const float*)d_in[0];
    const float* v     = (const float*)d_in[1];
    const float* Wq    = (const float*)d_in[2];
    const float* bq    = (const float*)d_in[3];
    const float* Wk    = (const float*)d_in[4];
    const float* bk    = (const float*)d_in[5];
    const float* Wv    = (const float*)d_in[6];
    const float* bv    = (const float*)d_in[7];
    const float* gamma = (const float*)d_in[8];
    float* out = (float*)d_out;

    static bf16 *pAq = nullptr, *pAv, *pW, *pT, *pF, *pG;
    static cudaStream_t s2;
    static cudaEvent_t evFork, evW, evTF, evG, evF1;
    if (!pAq) {
        cudaGetSymbolAddress((void**)&pAq, d_Aq);
        cudaGetSymbolAddress((void**)&pAv, d_Av);
        cudaGetSymbolAddress((void**)&pW,  d_W);
        cudaGetSymbolAddress((void**)&pT,  d_tb);
        cudaGetSymbolAddress((void**)&pF,  d_fb);
        cudaGetSymbolAddress((void**)&pG,  d_gb);
        cudaStreamCreateWithFlags(&s2, cudaStreamNonBlocking);
        cudaEventCreateWithFlags(&evFork, cudaEventDisableTiming);
        cudaEventCreateWithFlags(&evW,    cudaEventDisableTiming);
        cudaEventCreateWithFlags(&evTF,   cudaEventDisableTiming);
        cudaEventCreateWithFlags(&evG,    cudaEventDisableTiming);
        cudaEventCreateWithFlags(&evF1,   cudaEventDisableTiming);
    }

    const int smConv = NSTG * STGB;  // 81920
    const int smE    = 2 * ABUF;     // 27648
    const int smF    = G_OFF + ABUF; // 90624
    static bool attrs_set = false;
    if (!attrs_set) {
        cudaFuncSetAttribute(conv_wmma_kernel, cudaFuncAttributeMaxDynamicSharedMemorySize, smConv);
        cudaFuncSetAttribute(erow_kernel,      cudaFuncAttributeMaxDynamicSharedMemorySize, smE);
        cudaFuncSetAttribute(fusedcol_kernel,  cudaFuncAttributeMaxDynamicSharedMemorySize, smF);
        attrs_set = true;
    }

    // Fork s2 from the capture stream FIRST
    cudaEventRecord(evFork, 0);
    cudaStreamWaitEvent(s2, evFork, 0);

    // s2: toW, toA(v); main: toA(q)
    dim3 wGrid((CC * CC + 255) / 256, 3);
    toW_kernel<<<wGrid, 256, 0, s2>>>(Wq, Wk, Wv, pW);
    cudaEventRecord(evW, s2);

    dim3 spGrid(HW / 32, CC / 32, BB);
    toA_kernel<<<spGrid, 256, 0, s2>>>(v, pAv);   // conv-g input
    toA_kernel<<<spGrid, 256>>>(q, pAq);          // conv-tf input

    // conv-g on s2 (toW + toA(v) same stream)
    dim3 cg(MTOT / 128, CC / 128);
    conv_wmma_kernel<<<cg, 256, smConv, s2>>>(pAv, pW + 2 * CC * CC, bv, 1.0f, pG,
                                              bv, 1.0f, pG);
    cudaEventRecord(evG, s2);

    // fused t+f conv on main (toA(q) same stream; wait toW)
    cudaStreamWaitEvent(0, evW, 0);
    dim3 ctf(MTOT / 128, 2 * CC / 128);
    conv_wmma_kernel<<<ctf, 256, smConv>>>(pAq, pW, bq, SCALING, pT,
                                           bk, 1.0f, pF);
    cudaEventRecord(evTF, 0);

    // Attention pipelined over bh halves
    dim3 halfGrid(96, BHD / 2);

    // main: half 0
    erow_kernel<<<halfGrid, 256, smE>>>(0);

    // s2: half 1 (needs conv-tf)
    cudaStreamWaitEvent(s2, evTF, 0);
    erow_kernel<<<halfGrid, 256, smE, s2>>>(BHD / 2);
    fusedcol_kernel<<<halfGrid, 256, smF, s2>>>(BHD / 2);
    cudaEventRecord(evF1, s2);

    // main: fusedcol(h0) needs conv-g
    cudaStreamWaitEvent(0, evG, 0);
    fusedcol_kernel<<<halfGrid, 256, smF>>>(0);
    rowout_kernel<<<halfGrid, 256>>>(v, gamma, out, 0);

    // main: rowout(h1) after fusedcol(h1)
    cudaStreamWaitEvent(0, evF1, 0);
    rowout_kernel<<<halfGrid, 256>>>(v, gamma, out, BHD / 2);
}

// round 17
// speedup vs baseline: 1.0940x; 1.0221x over previous
#include <cuda_runtime.h>
#include <cuda_bf16.h>
#include <math.h>
#include <cstdint>

#define BB 4
#define NH 8
#define BHD 32
#define HH 96
#define WW 96
#define CC 512
#define DD 64
#define HW 9216
#define MTOT (BB * HW)      // 36864
#define SCALING 0.125f

typedef __nv_bfloat16 bf16;
typedef __nv_bfloat162 bf162;

// ---------------------------------------------------------------------------
// Device-global scratch
// ---------------------------------------------------------------------------
__device__ bf16 d_Er[(size_t)BHD * HW * 96];   // row logits (bf16)
__device__ bf16 d_Ar[(size_t)BHD * HW * 96];   // row probs (bf16)
__device__ bf16 d_O [(size_t)BHD * HW * DD];   // column partial (bf16)
__device__ bf16 d_tb[(size_t)BHD * HW * DD];
__device__ bf16 d_fb[(size_t)BHD * HW * DD];
__device__ bf16 d_gb[(size_t)BHD * HW * DD];
__device__ bf16 d_Aq[(size_t)MTOT * CC];
__device__ bf16 d_Av[(size_t)MTOT * CC];
__device__ bf16 d_W [3 * CC * CC];

// ---------------------------------------------------------------------------
// Helpers (generic PTX: sm_80+ features only)
// ---------------------------------------------------------------------------
__device__ __forceinline__ uint32_t smem_u32(const void* p) {
    uint32_t a;
    asm("{ .reg .u64 t; cvta.to.shared.u64 t, %1; cvt.u32.u64 %0, t; }" : "=r"(a) : "l"(p));
    return a;
}
__device__ __forceinline__ void cpa16(uint32_t d, const void* s) {
    asm volatile("cp.async.ca.shared.global [%0], [%1], 16;" :: "r"(d), "l"(s));
}
__device__ __forceinline__ void ldmx4(uint32_t* r, uint32_t addr) {
    asm volatile("ldmatrix.sync.aligned.m8n8.x4.shared.b16 {%0,%1,%2,%3}, [%4];"
        : "=r"(r[0]), "=r"(r[1]), "=r"(r[2]), "=r"(r[3]) : "r"(addr));
}
__device__ __forceinline__ void ldmxt4(uint32_t* r, uint32_t addr) {
    asm volatile("ldmatrix.sync.aligned.m8n8.x4.trans.shared.b16 {%0,%1,%2,%3}, [%4];"
        : "=r"(r[0]), "=r"(r[1]), "=r"(r[2]), "=r"(r[3]) : "r"(addr));
}
__device__ __forceinline__ void ldmx2(uint32_t* r, uint32_t addr) {
    asm volatile("ldmatrix.sync.aligned.m8n8.x2.shared.b16 {%0,%1}, [%2];"
        : "=r"(r[0]), "=r"(r[1]) : "r"(addr));
}
__device__ __forceinline__ void mma16816(float* c, const uint32_t* a,
                                         uint32_t b0, uint32_t b1) {
    asm volatile(
        "mma.sync.aligned.m16n8k16.row.col.f32.bf16.bf16.f32 "
        "{%0,%1,%2,%3}, {%4,%5,%6,%7}, {%8,%9}, {%0,%1,%2,%3};"
        : "+f"(c[0]), "+f"(c[1]), "+f"(c[2]), "+f"(c[3])
        : "r"(a[0]), "r"(a[1]), "r"(a[2]), "r"(a[3]), "r"(b0), "r"(b1));
}

// ---------------------------------------------------------------------------
// Prepass A: transpose + bf16 convert  X[b][c][px] -> A [m][c]
// ---------------------------------------------------------------------------
__global__ void __launch_bounds__(256) toA_kernel(
    const float* __restrict__ X, bf16* __restrict__ dst)
{
    __shared__ float tile[32][33];
    const int t   = threadIdx.x;
    const int px0 = blockIdx.x * 32;
    const int c0  = blockIdx.y * 32;
    const int b   = blockIdx.z;

#pragma unroll
    for (int r = 0; r < 4; r++) {
        int ci = (t >> 5) + r * 8, pj = t & 31;
        tile[ci][pj] = X[((size_t)b * CC + c0 + ci) * HW + px0 + pj];
    }
    __syncthreads();
#pragma unroll
    for (int r = 0; r < 4; r++) {
        int pj = (t >> 5) + r * 8, ci = t & 31;
        dst[((size_t)b * HW + px0 + pj) * CC + c0 + ci] = __float2bfloat16(tile[ci][pj]);
    }
}

__global__ void __launch_bounds__(256) toW_kernel(
    const float* __restrict__ W0, const float* __restrict__ W1,
    const float* __restrict__ W2, bf16* __restrict__ dst)
{
    const int w = blockIdx.y;
    const float* W = (w == 0) ? W0 : (w == 1) ? W1 : W2;
    int i = blockIdx.x * 256 + threadIdx.x;
    if (i < CC * CC) dst[(size_t)w * CC * CC + i] = __float2bfloat16(W[i]);
}

// ---------------------------------------------------------------------------
// Conv GEMM on mma.sync, cp.async 4-stage pipeline. 128x128 tile, K chunk 32.
// (8 warps, warp tile 32x64, 2 CTAs/SM.)  Fused double-output over [W1;W2].
// ---------------------------------------------------------------------------
#define KPAD 40
#define AOFF 0
#define BOFF (128 * KPAD * 2)       // 10240
#define STGB (2 * 128 * KPAD * 2)   // 20480
#define NSTG 4

__global__ void __launch_bounds__(256) conv_wmma_kernel(
    const bf16* __restrict__ A, const bf16* __restrict__ B,
    const float* __restrict__ bias, float scale, bf16* __restrict__ dst,
    const float* __restrict__ bias2, float scale2, bf16* __restrict__ dst2)
{
    extern __shared__ __align__(16) bf16 cs[];
    const uint32_t sb = smem_u32(cs);

    const int tid  = threadIdx.x;
    const int lane = tid & 31;
    const int warp = tid >> 5;
    const int wm   = warp & 3;
    const int wn   = warp >> 2;

    const int M0 = blockIdx.x * 128;
    const int o0 = blockIdx.y * 128;

    const int side = (o0 >= CC);
    const float* bb = side ? bias2 : bias;
    bf16* dd        = side ? dst2  : dst;
    const float sc  = side ? scale2 : scale;
    const int oo0   = o0 - side * CC;

    const int crow = tid >> 2, cseg = tid & 3;
    const bf16* pA = A + (size_t)(M0 + crow) * CC + cseg * 8;
    const bf16* pB = B + (size_t)(o0 + crow) * CC + cseg * 8;
    const uint32_t sdst = (crow * KPAD + cseg * 8) * 2;
    const uint32_t rstep = 64 * KPAD * 2;

    float acc[2][8][4];
#pragma unroll
    for (int mi = 0; mi < 2; mi++)
#pragma unroll
        for (int nf = 0; nf < 8; nf++)
#pragma unroll
            for (int k = 0; k < 4; k++) acc[mi][nf][k] = 0.f;

    const int lrow = lane & 15;
    const int lsel = (lane >> 4) * 8;

#pragma unroll
    for (int p = 0; p < 3; p++) {
        uint32_t so = sb + p * STGB + sdst;
#pragma unroll
        for (int r = 0; r < 2; r++) {
            const size_t go = (size_t)r * 64 * CC + p * 32;
            cpa16(so + AOFF + r * rstep, pA + go);
            cpa16(so + BOFF + r * rstep, pB + go);
        }
        asm volatile("cp.async.commit_group;");
    }

    for (int ch = 0; ch < 16; ch++) {
        if (ch + 3 < 16) {
            uint32_t so = sb + ((ch + 3) % NSTG) * STGB + sdst;
#pragma unroll
            for (int r = 0; r < 2; r++) {
                const size_t go = (size_t)r * 64 * CC + (ch + 3) * 32;
                cpa16(so + AOFF + r * rstep, pA + go);
                cpa16(so + BOFF + r * rstep, pB + go);
            }
            asm volatile("cp.async.commit_group;");
            asm volatile("cp.async.wait_group 3;");
        } else if (ch + 2 < 16) {
            asm volatile("cp.async.wait_group 2;");
        } else if (ch + 1 < 16) {
            asm volatile("cp.async.wait_group 1;");
        } else {
            asm volatile("cp.async.wait_group 0;");
        }
        __syncthreads();

        const uint32_t stb = sb + (ch % NSTG) * STGB;
#pragma unroll
        for (int ks = 0; ks < 2; ks++) {
            const int kc = ks * 16 + lsel;
            uint32_t a[2][4];
#pragma unroll
            for (int mi = 0; mi < 2; mi++)
                ldmx4(a[mi], stb + AOFF + ((wm * 32 + mi * 16 + lrow) * KPAD + kc) * 2);
#pragma unroll
            for (int np = 0; np < 4; np++) {
                uint32_t b[4];
                ldmx4(b, stb + BOFF + ((wn * 64 + np * 16 + lrow) * KPAD + kc) * 2);
#pragma unroll
                for (int mi = 0; mi < 2; mi++)
#pragma unroll
                    for (int hf = 0; hf < 2; hf++)
                        mma16816(acc[mi][np * 2 + hf], a[mi], b[hf], b[2 + hf]);
            }
        }
        __syncthreads();
    }

#pragma unroll
    for (int mi = 0; mi < 2; mi++) {
        const int m  = M0 + wm * 32 + mi * 16 + (lane >> 2);
        const int b  = m / HW;
        const int pp = m % HW;
#pragma unroll
        for (int nf = 0; nf < 8; nf++) {
            const int o = oo0 + wn * 64 + nf * 8 + (lane & 3) * 2;
            const int h = o >> 6, d = o & 63;
            const float b0 = bb[o], b1 = bb[o + 1];
            size_t i0 = ((size_t)(b * NH + h) * HW + pp) * DD + d;
            size_t i1 = i0 + (size_t)8 * DD;
            *(bf162*)(dd + i0) = bf162{
                __float2bfloat16((acc[mi][nf][0] + b0) * sc),
                __float2bfloat16((acc[mi][nf][1] + b1) * sc)};
            *(bf162*)(dd + i1) = bf162{
                __float2bfloat16((acc[mi][nf][2] + b0) * sc),
                __float2bfloat16((acc[mi][nf][3] + b1) * sc)};
        }
    }
}

// ---------------------------------------------------------------------------
// Logits mma: C[96][96] = A[96][64] * B[96][64]^T, bf16, pitch 72.
// ---------------------------------------------------------------------------
#define PBF 72
#define ABUF 13824   // 96*72*2

__device__ __forceinline__ void logits_mma(
    uint32_t sb, uint32_t aOff, uint32_t bOff, int lane, int wm, int wn,
    float acc[3][3][4])
{
    const int l15 = lane & 15;
#pragma unroll
    for (int ks = 0; ks < 4; ks++) {
        const int kc = ks * 16;
        uint32_t a[3][4];
#pragma unroll
        for (int mt = 0; mt < 3; mt++)
            ldmx4(a[mt], sb + aOff +
                ((wm * 48 + mt * 16 + l15) * PBF + kc + (lane >> 4) * 8) * 2);
#pragma unroll
        for (int nt = 0; nt < 3; nt++) {
            uint32_t b[2];
            ldmx2(b, sb + bOff +
                ((wn * 24 + nt * 8 + (l15 & 7)) * PBF + kc + ((l15 >> 3) & 1) * 8) * 2);
#pragma unroll
            for (int mt = 0; mt < 3; mt++)
                mma16816(acc[mt][nt], a[mt], b[0], b[1]);
        }
    }
}

// Output mma: C[96][64] = A[96][96](pitch APITCH bf16) * B[96][64](pitch 72, trans)
#define PA 104

template <int APITCH>
__device__ __forceinline__ void probs_mma(
    uint32_t sb, uint32_t aOff, uint32_t gOff, int lane, int wm, int wn,
    float acc[3][2][4])
{
    const int l15 = lane & 15;
#pragma unroll
    for (int ks = 0; ks < 6; ks++) {
        const int kc = ks * 16;
        uint32_t a[3][4];
#pragma unroll
        for (int mt = 0; mt < 3; mt++)
            ldmx4(a[mt], sb + aOff +
                ((wm * 48 + mt * 16 + l15) * APITCH + kc + (lane >> 4) * 8) * 2);
        uint32_t bt[4];
        ldmxt4(bt, sb + gOff + ((kc + l15) * PBF + wn * 16 + (lane >> 4) * 8) * 2);
#pragma unroll
        for (int mt = 0; mt < 3; mt++) {
            mma16816(acc[mt][0], a[mt], bt[0], bt[1]);
            mma16816(acc[mt][1], a[mt], bt[2], bt[3]);
        }
    }
}

// ---------------------------------------------------------------------------
// Kernel 2: row logits -> d_Er (bf16). Block (y, bh-bh0).
// ---------------------------------------------------------------------------
__global__ void __launch_bounds__(256) erow_kernel(int bh0)
{
    extern __shared__ __align__(16) char smem[];
    const uint32_t sb = smem_u32(smem);

    const int y = blockIdx.x, bh = blockIdx.y + bh0, tid = threadIdx.x;
    const int lane = tid & 31, warp = tid >> 5;

    const size_t off = ((size_t)bh * HW + y * 96) * DD;
    const bf16* srcs[2] = {d_tb + off, d_fb + off};
#pragma unroll
    for (int a = 0; a < 2; a++)
#pragma unroll
        for (int k = 0; k < 3; k++) {
            int idx = tid + k * 256;
            int row = idx >> 3, c = (idx & 7) * 8;
            *(uint4*)(smem + a * ABUF + (row * PBF + c) * 2) =
                *(const uint4*)(srcs[a] + (size_t)idx * 8);
        }
    __syncthreads();

    float acc[3][3][4];
#pragma unroll
    for (int mt = 0; mt < 3; mt++)
#pragma unroll
        for (int nt = 0; nt < 3; nt++)
#pragma unroll
            for (int k = 0; k < 4; k++) acc[mt][nt][k] = 0.f;

    const int wm = warp >> 2, wn = warp & 3;
    logits_mma(sb, 0, ABUF, lane, wm, wn, acc);

    bf16* Eb = d_Er + ((size_t)bh * HH + y) * WW * 96;
#pragma unroll
    for (int mt = 0; mt < 3; mt++)
#pragma unroll
        for (int nt = 0; nt < 3; nt++) {
            const int x0 = wm * 48 + mt * 16 + (lane >> 2);
            const int i0 = wn * 24 + nt * 8 + (lane & 3) * 2;
            *(bf162*)&Eb[(size_t)x0 * 96 + i0] = bf162{
                __float2bfloat16(acc[mt][nt][0]), __float2bfloat16(acc[mt][nt][1])};
            *(bf162*)&Eb[(size_t)(x0 + 8) * 96 + i0] = bf162{
                __float2bfloat16(acc[mt][nt][2]), __float2bfloat16(acc[mt][nt][3])};
        }
}

// ---------------------------------------------------------------------------
// Kernel 3 (fused): per (x, bh-bh0): col logits + softmax(192) + prob emission
//   + column output (mma) -> d_O (bf16).
// ---------------------------------------------------------------------------
#define EC_OFF 38400
#define G_OFF  76800
#define PAC 200

__global__ void __launch_bounds__(256) fusedcol_kernel(int bh0)
{
    extern __shared__ __align__(16) char smem[];
    const uint32_t sb = smem_u32(smem);

    const int x = blockIdx.x, bh = blockIdx.y + bh0, tid = threadIdx.x;
    const int lane = tid & 31, warp = tid >> 5;
    const int wm = warp >> 2, wn = warp & 3;

    // P1 load: t/f columns (row stride WW*DD)
    {
        const size_t off = ((size_t)bh * HW + x) * DD;
        const bf16* srcs[2] = {d_tb + off, d_fb + off};
#pragma unroll
        for (int a = 0; a < 2; a++)
#pragma unroll
            for (int k = 0; k < 3; k++) {
                int idx = tid + k * 256;
                int row = idx >> 3, c = (idx & 7) * 8;
                *(uint4*)(smem + a * ABUF + (row * PBF + c) * 2) =
                    *(const uint4*)(srcs[a] + (size_t)row * (WW * DD) + c);
            }
    }
    __syncthreads();

    // column logits -> Ec with diagonal mask
    {
        float acc[3][3][4];
#pragma unroll
        for (int mt = 0; mt < 3; mt++)
#pragma unroll
            for (int nt = 0; nt < 3; nt++)
#pragma unroll
                for (int k = 0; k < 4; k++) acc[mt][nt][k] = 0.f;

        logits_mma(sb, 0, ABUF, lane, wm, wn, acc);

        float (*Ec)[100] = (float(*)[100])(smem + EC_OFF);
#pragma unroll
        for (int mt = 0; mt < 3; mt++)
#pragma unroll
            for (int nt = 0; nt < 3; nt++) {
                const int y0 = wm * 48 + mt * 16 + (lane >> 2);
                const int i0 = wn * 24 + nt * 8 + (lane & 3) * 2;
                Ec[y0][i0]     = (i0     == y0)     ? -INFINITY : acc[mt][nt][0];
                Ec[y0][i0 + 1] = (i0 + 1 == y0)     ? -INFINITY : acc[mt][nt][1];
                Ec[y0 + 8][i0]     = (i0     == y0 + 8) ? -INFINITY : acc[mt][nt][2];
                Ec[y0 + 8][i0 + 1] = (i0 + 1 == y0 + 8) ? -INFINITY : acc[mt][nt][3];
            }
    }
    __syncthreads();

    // P2 loads: Er slice (bf16 -> fp32 smem) + g column
    {
        float (*Er)[100] = (float(*)[100])smem;
        const bf16* eb = d_Er + (size_t)bh * HW * 96 + (size_t)x * 96;
        for (int idx = tid; idx < 96 * 12; idx += 256) {
            int r = idx / 12, c8 = idx % 12;
            uint4 raw = *(const uint4*)(eb + (size_t)r * (WW * 96) + c8 * 8);
            const bf162* pr = (const bf162*)&raw;
#pragma unroll
            for (int j = 0; j < 4; j++) {
                float2 f = __bfloat1622float2(pr[j]);
                Er[r][c8 * 8 + j * 2]     = f.x;
                Er[r][c8 * 8 + j * 2 + 1] = f.y;
            }
        }
        const bf16* gsrc = d_gb + ((size_t)bh * HW + x) * DD;
#pragma unroll
        for (int k = 0; k < 3; k++) {
            int idx = tid + k * 256;
            int row = idx >> 3, c = (idx & 7) * 8;
            *(uint4*)(smem + G_OFF + (row * PBF + c) * 2) =
                *(const uint4*)(gsrc + (size_t)row * (WW * DD) + c);
        }
    }
    __syncthreads();

    // softmax over concat(Er, Ec) — warp per row; emits probs directly
    {
        float (*Er)[100] = (float(*)[100])smem;
        float (*Ec)[100] = (float(*)[100])(smem + EC_OFF);
        bf16* Ac = (bf16*)smem;
#pragma unroll 1
        for (int rr = 0; rr < 12; rr++) {
            const int r = warp * 12 + rr;
            float vr[3], vc[3];
#pragma unroll
            for (int k = 0; k < 3; k++) { vr[k] = Er[r][lane + k * 32]; vc[k] = Ec[r][lane + k * 32]; }
            float m = -INFINITY;
#pragma unroll
            for (int k = 0; k < 3; k++) m = fmaxf(m, fmaxf(vr[k], vc[k]));
#pragma unroll
            for (int off = 16; off; off >>= 1) m = fmaxf(m, __shfl_xor_sync(0xffffffffu, m, off));
            float s = 0.f;
#pragma unroll
            for (int k = 0; k < 3; k++) {
                vr[k] = __expf(vr[k] - m); vc[k] = __expf(vc[k] - m);
                s += vr[k] + vc[k];
            }
#pragma unroll
            for (int off = 16; off; off >>= 1) s += __shfl_xor_sync(0xffffffffu, s, off);
            const float inv = 1.f / s;
            bf16* arow = d_Ar + ((size_t)(bh * HH + r) * WW + x) * 96;
            bf16* acrow = Ac + r * PAC;
#pragma unroll
            for (int k = 0; k < 3; k++) {
                arow[lane + k * 32]  = __float2bfloat16(vr[k] * inv);
                acrow[lane + k * 32] = __float2bfloat16(vc[k] * inv);
            }
        }
    }
    __syncthreads();

    // column output mma -> d_O (bf16)
    {
        float acc[3][2][4];
#pragma unroll
        for (int mt = 0; mt < 3; mt++)
#pragma unroll
            for (int nt = 0; nt < 2; nt++)
#pragma unroll
                for (int k = 0; k < 4; k++) acc[mt][nt][k] = 0.f;

        probs_mma<PAC>(sb, 0, G_OFF, lane, wm, wn, acc);

#pragma unroll
        for (int mt = 0; mt < 3; mt++)
#pragma unroll
            for (int nt = 0; nt < 2; nt++) {
                const int yv = wm * 48 + mt * 16 + (lane >> 2);
                const int d0 = wn * 16 + nt * 8 + (lane & 3) * 2;
                bf16* ob = d_O + ((size_t)(bh * HH + yv) * WW + x) * DD + d0;
                *(bf162*)ob = bf162{
                    __float2bfloat16(acc[mt][nt][0]), __float2bfloat16(acc[mt][nt][1])};
                *(bf162*)(ob + (size_t)8 * WW * DD) = bf162{
                    __float2bfloat16(acc[mt][nt][2]), __float2bfloat16(acc[mt][nt][3])};
            }
    }
}

// ---------------------------------------------------------------------------
// Kernel 4: row output (mma) + combine + residual. Block (y, bh-bh0).
// ---------------------------------------------------------------------------
__global__ void __launch_bounds__(256) rowout_kernel(
    const float* __restrict__ v, const float* __restrict__ gamma,
    float* __restrict__ out, int bh0)
{
    __shared__ __align__(16) bf16 Asm[96][PA];
    __shared__ __align__(16) bf16 gsm[96][PBF];

    const int y = blockIdx.x, bh = blockIdx.y + bh0, tid = threadIdx.x;
    const int lane = tid & 31, warp = tid >> 5;
    const int wm = warp >> 2, wn = warp & 3;

    const bf16* ab = d_Ar + ((size_t)bh * HH + y) * WW * 96;
    for (int idx = tid; idx < 96 * 12; idx += 256) {
        int row = idx / 12, c8 = idx % 12;
        *(uint4*)&Asm[row][c8 * 8] = *(const uint4*)(ab + (size_t)row * 96 + c8 * 8);
    }
    const bf16* gb = d_gb + ((size_t)bh * HH + y) * WW * DD;
#pragma unroll
    for (int k = 0; k < 3; k++) {
        int idx = tid + k * 256;
        int row = idx >> 3, c = (idx & 7) * 8;
        *(uint4*)&gsm[row][c] = *(const uint4*)(gb + (size_t)idx * 8);
    }
    __syncthreads();

    float acc[3][2][4];
#pragma unroll
    for (int mt = 0; mt < 3; mt++)
#pragma unroll
        for (int nt = 0; nt < 2; nt++)
#pragma unroll
            for (int k = 0; k < 4; k++) acc[mt][nt][k] = 0.f;

    const uint32_t sbA = smem_u32(Asm);
    const uint32_t sbG = smem_u32(gsm);
    probs_mma<PA>(sbA, 0, sbG - sbA, lane, wm, wn, acc);

    const float gam = gamma[0];
    const int b = bh >> 3, h = bh & 7;
    const bf16* colp = d_O + ((size_t)bh * HH + y) * WW * DD;

#pragma unroll
    for (int mt = 0; mt < 3; mt++)
#pragma unroll
        for (int nt = 0; nt < 2; nt++) {
            const int x0 = wm * 48 + mt * 16 + (lane >> 2);
            const int d0 = wn * 16 + nt * 8 + (lane & 3) * 2;
#pragma unroll
            for (int rh = 0; rh < 2; rh++) {
                const int xx = x0 + rh * 8;
                float2 cp = __bfloat1622float2(
                    *(const bf162*)(colp + (size_t)xx * DD + d0));
                float s0 = acc[mt][nt][rh * 2]     + cp.x;
                float s1 = acc[mt][nt][rh * 2 + 1] + cp.y;
                size_t oa0 = (((size_t)(b * CC + h * 64 + d0)) * HH + y) * WW + xx;
                size_t oa1 = oa0 + (size_t)HW;
                out[oa0] = gam * s0 + v[oa0];
                out[oa1] = gam * s1 + v[oa1];
            }
        }
}

// ---------------------------------------------------------------------------
extern "C" void kernel_launch(void* const* d_in, const int* in_sizes, int n_in,
                              void* d_out, int out_size)
{
    const float* q     = (const float*)d_in[0];
    const float* v     = (const float*)d_in[1];
    const float* Wq    = (const float*)d_in[2];
    const float* bq    = (const float*)d_in[3];
    const float* Wk    = (const float*)d_in[4];
    const float* bk    = (const float*)d_in[5];
    const float* Wv    = (const float*)d_in[6];
    const float* bv    = (const float*)d_in[7];
    const float* gamma = (const float*)d_in[8];
    float* out = (float*)d_out;

    static bf16 *pAq = nullptr, *pAv, *pW, *pT, *pF, *pG;
    static cudaStream_t s2;
    static cudaEvent_t evFork, evW, evTF, evG, evS2;
    if (!pAq) {
        cudaGetSymbolAddress((void**)&pAq, d_Aq);
        cudaGetSymbolAddress((void**)&pAv, d_Av);
        cudaGetSymbolAddress((void**)&pW,  d_W);
        cudaGetSymbolAddress((void**)&pT,  d_tb);
        cudaGetSymbolAddress((void**)&pF,  d_fb);
        cudaGetSymbolAddress((void**)&pG,  d_gb);
        cudaStreamCreateWithFlags(&s2, cudaStreamNonBlocking);
        cudaEventCreateWithFlags(&evFork, cudaEventDisableTiming);
        cudaEventCreateWithFlags(&evW,    cudaEventDisableTiming);
        cudaEventCreateWithFlags(&evTF,   cudaEventDisableTiming);
        cudaEventCreateWithFlags(&evG,    cudaEventDisableTiming);
        cudaEventCreateWithFlags(&evS2,   cudaEventDisableTiming);
    }

    const int smConv = NSTG * STGB;  // 81920
    const int smE    = 2 * ABUF;     // 27648
    const int smF    = G_OFF + ABUF; // 90624
    static bool attrs_set = false;
    if (!attrs_set) {
        cudaFuncSetAttribute(conv_wmma_kernel, cudaFuncAttributeMaxDynamicSharedMemorySize, smConv);
        cudaFuncSetAttribute(erow_kernel,      cudaFuncAttributeMaxDynamicSharedMemorySize, smE);
        cudaFuncSetAttribute(fusedcol_kernel,  cudaFuncAttributeMaxDynamicSharedMemorySize, smF);
        attrs_set = true;
    }

    // Fork s2 from the capture stream FIRST
    cudaEventRecord(evFork, 0);
    cudaStreamWaitEvent(s2, evFork, 0);

    // s2: toW, toA(v); main: toA(q)
    dim3 wGrid((CC * CC + 255) / 256, 3);
    toW_kernel<<<wGrid, 256, 0, s2>>>(Wq, Wk, Wv, pW);
    cudaEventRecord(evW, s2);

    dim3 spGrid(HW / 32, CC / 32, BB);
    toA_kernel<<<spGrid, 256, 0, s2>>>(v, pAv);   // conv-g input
    toA_kernel<<<spGrid, 256>>>(q, pAq);          // conv-tf input

    // conv-g on s2 (toW + toA(v) same stream)
    dim3 cg(MTOT / 128, CC / 128);
    conv_wmma_kernel<<<cg, 256, smConv, s2>>>(pAv, pW + 2 * CC * CC, bv, 1.0f, pG,
                                              bv, 1.0f, pG);
    cudaEventRecord(evG, s2);

    // fused t+f conv on main (toA(q) same stream; wait toW)
    cudaStreamWaitEvent(0, evW, 0);
    dim3 ctf(MTOT / 128, 2 * CC / 128);
    conv_wmma_kernel<<<ctf, 256, smConv>>>(pAq, pW, bq, SCALING, pT,
                                           bk, 1.0f, pF);
    cudaEventRecord(evTF, 0);

    // Attention: symmetric half-chains on both streams
    dim3 halfGrid(96, BHD / 2);

    // main: half 0 (erow after conv-tf same stream; fusedcol needs conv-g)
    erow_kernel<<<halfGrid, 256, smE>>>(0);
    cudaStreamWaitEvent(0, evG, 0);
    fusedcol_kernel<<<halfGrid, 256, smF>>>(0);
    rowout_kernel<<<halfGrid, 256>>>(v, gamma, out, 0);

    // s2: half 1 (needs conv-tf; g already on s2)
    cudaStreamWaitEvent(s2, evTF, 0);
    erow_kernel<<<halfGrid, 256, smE, s2>>>(BHD / 2);
    fusedcol_kernel<<<halfGrid, 256, smF, s2>>>(BHD / 2);
    rowout_kernel<<<halfGrid, 256, 0, s2>>>(v, gamma, out, BHD / 2);
    cudaEventRecord(evS2, s2);

    // join s2 back into the capture stream
    cudaStreamWaitEvent(0, evS2, 0);
}